// round 3
// baseline (speedup 1.0000x reference)
#include <cuda_runtime.h>
#include <math.h>

#define Bc 2
#define Sc 2048
#define Tc 8
#define Cc 128
#define Kc 16
#define Hc 4
#define Dc 32
#define Fc 130        // C+2
#define F2c 132       // padded row for smem
#define BTc (Bc*Tc)   // 16
#define Nc (BTc*Sc)   // 32768
#define Uc (Hc*Fc)    // 520

typedef unsigned long long u64;

// ---- scratch (no allocations allowed; __device__ globals) ----
__device__ float g_Wu[Cc*Uc];             // [c][h*F+f]  (1/sqrt(D) folded in)
__device__ float g_WoT[Uc*Cc];            // [h*F+f][c']
__device__ float g_U[(size_t)Nc*Uc];      // 68 MB
__device__ float g_NB[(size_t)Nc*Uc];     // 68 MB
__device__ int   g_is64;

// packed fp32x2 helpers
__device__ __forceinline__ void fma2(u64& d, u64 a, u64 b) {
    asm("fma.rn.f32x2 %0, %1, %2, %0;" : "+l"(d) : "l"(a), "l"(b));
}
__device__ __forceinline__ u64 pack2(float lo, float hi) {
    u64 r;
    asm("mov.b64 %0, {%1, %2};" : "=l"(r) : "f"(lo), "f"(hi));
    return r;
}
__device__ __forceinline__ void unpack2(u64 v, float& lo, float& hi) {
    asm("mov.b64 {%0, %1}, %2;" : "=f"(lo), "=f"(hi) : "l"(v));
}
__device__ __forceinline__ u64 dup2(float w) { return pack2(w, w); }

// ---------------------------------------------------------------------------
__global__ void k_detect(const unsigned int* __restrict__ p) {
    __shared__ int any;
    if (threadIdx.x == 0) any = 0;
    __syncthreads();
    for (int i = threadIdx.x; i < 4096; i += blockDim.x)
        if (p[2*i + 1] != 0u) any = 1;
    __syncthreads();
    if (threadIdx.x == 0) g_is64 = (any == 0) ? 1 : 0;
}

// ---------------------------------------------------------------------------
// k0: combined weights.
//   W_u[c][h*F+f]   = (1/sqrt(D)) * sum_d Wq[h*D+d, c] * Wk[h*D+d, f]
//   W_oT[h*F+f][c'] =               sum_d Wp[c', h*D+d] * Wv[h*D+d, f]
// ---------------------------------------------------------------------------
__global__ void k0_combine(const float* __restrict__ Wq, const float* __restrict__ Wk,
                           const float* __restrict__ Wv, const float* __restrict__ Wp) {
    int i = blockIdx.x * blockDim.x + threadIdx.x;
    if (i >= Cc*Uc) return;
    int c = i / Uc;
    int j = i % Uc;
    int h = j / Fc;
    int f = j % Fc;
    float su = 0.f, so = 0.f;
    #pragma unroll
    for (int d = 0; d < Dc; d++) {
        int hd = h*Dc + d;
        su = fmaf(Wq[hd*Cc + c], Wk[hd*(Cc+2) + f], su);
        so = fmaf(Wp[c*Cc + hd], Wv[hd*(Cc+2) + f], so);
    }
    g_Wu[c*Uc + j]  = su * rsqrtf((float)Dc);
    g_WoT[j*Cc + c] = so;
}

// ---------------------------------------------------------------------------
// k1: U = X_ @ W_u. 32 rows/block (16 row-pairs), 544 threads.
// Thread tile: 4 row-pairs (rpg = tid/136) x 4 j (jg = tid%136, jg<130).
// Per c: 2 LDS.128 (broadcast) + 1 LDG.128 (w) + 16 fma2.
// ---------------------------------------------------------------------------
__global__ __launch_bounds__(544) void k1_u(const float* __restrict__ x) {
    __shared__ __align__(16) u64 xs2[Cc*16];   // [c][rp], 16 KB
    int base = blockIdx.x * 32;
    int bt = base >> 11;
    int s0 = base & 2047;
    int b = bt >> 3, t = bt & 7;
    int tid = threadIdx.x;

    if (tid < 512) {
        int rp = tid & 15, c4 = tid >> 4;        // c4 in 0..31
        const float* r0 = x + ((size_t)((b*Sc + s0 + 2*rp)*Tc + t)) * Cc;
        const float* r1 = r0 + (size_t)Tc * Cc;
        float4 a  = ((const float4*)r0)[c4];
        float4 bb = ((const float4*)r1)[c4];
        int c = 4*c4;
        xs2[(c+0)*16 + rp] = pack2(a.x, bb.x);
        xs2[(c+1)*16 + rp] = pack2(a.y, bb.y);
        xs2[(c+2)*16 + rp] = pack2(a.z, bb.z);
        xs2[(c+3)*16 + rp] = pack2(a.w, bb.w);
    }
    __syncthreads();

    int rpg = tid / 136;          // 0..3
    int jg  = tid % 136;          // 0..135, active < 130
    if (jg >= 130) return;
    int j0 = jg * 4;

    u64 acc[4][4];
    #pragma unroll
    for (int r = 0; r < 4; r++)
        #pragma unroll
        for (int e = 0; e < 4; e++) acc[r][e] = 0ull;

    const float4* wrow = (const float4*)(g_Wu);  // row stride Uc/4 float4
    #pragma unroll 2
    for (int c = 0; c < Cc; c++) {
        float4 w = ((const float4*)(g_Wu + c*Uc))[jg];
        u64 w0 = dup2(w.x), w1 = dup2(w.y), w2 = dup2(w.z), w3 = dup2(w.w);
        ulonglong2 xa = *((const ulonglong2*)&xs2[c*16 + rpg*4]);
        ulonglong2 xb = *((const ulonglong2*)&xs2[c*16 + rpg*4 + 2]);
        u64 xv[4] = {xa.x, xa.y, xb.x, xb.y};
        #pragma unroll
        for (int r = 0; r < 4; r++) {
            fma2(acc[r][0], xv[r], w0);
            fma2(acc[r][1], xv[r], w1);
            fma2(acc[r][2], xv[r], w2);
            fma2(acc[r][3], xv[r], w3);
        }
    }
    (void)wrow;

    #pragma unroll
    for (int r = 0; r < 4; r++) {
        int rp = rpg*4 + r;
        float lo0, hi0, lo1, hi1, lo2, hi2, lo3, hi3;
        unpack2(acc[r][0], lo0, hi0);
        unpack2(acc[r][1], lo1, hi1);
        unpack2(acc[r][2], lo2, hi2);
        unpack2(acc[r][3], lo3, hi3);
        float4 vlo = make_float4(lo0, lo1, lo2, lo3);
        float4 vhi = make_float4(hi0, hi1, hi2, hi3);
        ((float4*)(g_U + (size_t)(base + 2*rp    )*Uc))[jg] = vlo;
        ((float4*)(g_U + (size_t)(base + 2*rp + 1)*Uc))[jg] = vhi;
    }
}

// ---------------------------------------------------------------------------
// k2: per (bt,s): gather K neighbors, logits (float4), softmax, nbar.
// ---------------------------------------------------------------------------
__global__ __launch_bounds__(128, 8) void k2_attn(const float* __restrict__ x,
                                                  const void* __restrict__ sidx,
                                                  const float* __restrict__ swgt,
                                                  const float* __restrict__ ali,
                                                  const float* __restrict__ dstp) {
    __shared__ __align__(16) float nb[Kc][F2c];   // K x 132
    __shared__ __align__(16) float us[Hc*F2c];    // 4 x 132 padded
    __shared__ float lg[Hc][Kc];
    __shared__ float attn_s[Hc][Kc];

    int n = blockIdx.x;
    int bt = n >> 11;
    int b = bt >> 3, t = bt & 7;
    int tid = threadIdx.x;

    // gather neighbors: 8 threads per k (start loads first — longest latency)
    int k = tid >> 3, l8 = tid & 7;
    long long jn;
    if (g_is64) jn = ((const long long*)sidx)[(size_t)n*Kc + k];
    else        jn = (long long)((const int*)sidx)[(size_t)n*Kc + k];
    const float4* src = (const float4*)(x + ((size_t)((b*Sc + (int)jn)*Tc + t)) * Cc);
    #pragma unroll
    for (int q = 0; q < 4; q++) {
        int f4 = l8 + q*8;
        *((float4*)&nb[k][f4*4]) = src[f4];
    }
    if (l8 == 0) {
        nb[k][128] = ali [(size_t)n*Kc + k];
        nb[k][129] = dstp[(size_t)n*Kc + k];
    }

    // load u (520 floats) into padded us
    {
        const float4* row4 = (const float4*)(g_U + (size_t)n*Uc);
        for (int i4 = tid; i4 < Uc/4; i4 += 128) {
            float4 v = row4[i4];
            int j = 4*i4;
            us[(j    )/Fc * F2c + (j    )%Fc] = v.x;
            us[(j + 1)/Fc * F2c + (j + 1)%Fc] = v.y;
            us[(j + 2)/Fc * F2c + (j + 2)%Fc] = v.z;
            us[(j + 3)/Fc * F2c + (j + 3)%Fc] = v.w;
        }
    }
    __syncthreads();

    // logits: thread (k,l8): float4 over f, 4 head partials, reduce over 8 lanes
    {
        float p0 = 0.f, p1 = 0.f, p2 = 0.f, p3 = 0.f;
        #pragma unroll
        for (int q = 0; q < 4; q++) {
            int f4 = l8 + q*8;
            float4 v  = *((const float4*)&nb[k][f4*4]);
            float4 u0 = *((const float4*)&us[0*F2c + f4*4]);
            float4 u1 = *((const float4*)&us[1*F2c + f4*4]);
            float4 u2 = *((const float4*)&us[2*F2c + f4*4]);
            float4 u3 = *((const float4*)&us[3*F2c + f4*4]);
            p0 = fmaf(u0.x,v.x,fmaf(u0.y,v.y,fmaf(u0.z,v.z,fmaf(u0.w,v.w,p0))));
            p1 = fmaf(u1.x,v.x,fmaf(u1.y,v.y,fmaf(u1.z,v.z,fmaf(u1.w,v.w,p1))));
            p2 = fmaf(u2.x,v.x,fmaf(u2.y,v.y,fmaf(u2.z,v.z,fmaf(u2.w,v.w,p2))));
            p3 = fmaf(u3.x,v.x,fmaf(u3.y,v.y,fmaf(u3.z,v.z,fmaf(u3.w,v.w,p3))));
        }
        if (l8 < 2) {       // tail f = 128, 129
            int f = 128 + l8;
            float v = nb[k][f];
            p0 = fmaf(us[0*F2c + f], v, p0);
            p1 = fmaf(us[1*F2c + f], v, p1);
            p2 = fmaf(us[2*F2c + f], v, p2);
            p3 = fmaf(us[3*F2c + f], v, p3);
        }
        #pragma unroll
        for (int o = 4; o >= 1; o >>= 1) {
            p0 += __shfl_xor_sync(0xffffffffu, p0, o, 8);
            p1 += __shfl_xor_sync(0xffffffffu, p1, o, 8);
            p2 += __shfl_xor_sync(0xffffffffu, p2, o, 8);
            p3 += __shfl_xor_sync(0xffffffffu, p3, o, 8);
        }
        if (l8 == 0) { lg[0][k] = p0; lg[1][k] = p1; lg[2][k] = p2; lg[3][k] = p3; }
    }
    __syncthreads();

    // softmax over k (64 threads: h = tid/16, k = tid%16)
    if (tid < Hc*Kc) {
        int h = tid >> 4, kk = tid & 15;
        float lgv = lg[h][kk] + __logf(swgt[(size_t)n*Kc + kk] + 1e-6f);
        float m = lgv;
        #pragma unroll
        for (int o = 8; o >= 1; o >>= 1)
            m = fmaxf(m, __shfl_xor_sync(0xffffffffu, m, o, 16));
        float e = __expf(lgv - m);
        float ssum = e;
        #pragma unroll
        for (int o = 8; o >= 1; o >>= 1)
            ssum += __shfl_xor_sync(0xffffffffu, ssum, o, 16);
        attn_s[h][kk] = e / ssum;
    }
    __syncthreads();

    // nbar: thread = f; read nb[k][f] once, 4 head accumulators
    for (int f = tid; f < Fc; f += 128) {
        float a0 = 0.f, a1 = 0.f, a2 = 0.f, a3 = 0.f;
        #pragma unroll
        for (int kk = 0; kk < Kc; kk++) {
            float v = nb[kk][f];
            a0 = fmaf(attn_s[0][kk], v, a0);
            a1 = fmaf(attn_s[1][kk], v, a1);
            a2 = fmaf(attn_s[2][kk], v, a2);
            a3 = fmaf(attn_s[3][kk], v, a3);
        }
        float* dst = g_NB + (size_t)n*Uc;
        dst[0*Fc + f] = a0;
        dst[1*Fc + f] = a1;
        dst[2*Fc + f] = a2;
        dst[3*Fc + f] = a3;
    }
}

// ---------------------------------------------------------------------------
// k3: OUT = NB @ W_oT + bp. 64 rows/block (32 rp), 256 threads.
// Thread tile: 4 rp (rpg = tid/32) x 4 cp (jg = tid%32). j staged in 4 chunks
// of 130 (34KB smem). Per j: 2 LDS.128 (bcast) + 1 LDG.128 (w) + 16 fma2.
// ---------------------------------------------------------------------------
__global__ __launch_bounds__(256) void k3_out(const float* __restrict__ bp,
                                              float* __restrict__ out) {
    __shared__ __align__(16) u64 nbs2[130*32];   // [j_local][rp], 33.3 KB
    int base = blockIdx.x * 64;
    int bt = base >> 11;
    int s0 = base & 2047;
    int b = bt >> 3, t = bt & 7;
    int tid = threadIdx.x;
    int rpg = tid >> 5;       // 0..7
    int jg  = tid & 31;       // 0..31

    u64 acc[4][4];
    #pragma unroll
    for (int r = 0; r < 4; r++)
        #pragma unroll
        for (int e = 0; e < 4; e++) acc[r][e] = 0ull;

    for (int ch = 0; ch < 4; ch++) {
        __syncthreads();
        // stage chunk: 64 rows x 130 j as row-pair packs (float2 granularity)
        for (int task = tid; task < 32*65; task += 256) {
            int rp = task & 31, j2 = task >> 5;   // j2 in 0..64
            const float* r0 = g_NB + (size_t)(base + 2*rp)*Uc + ch*130;
            const float* r1 = r0 + Uc;
            float2 a  = ((const float2*)r0)[j2];
            float2 bb = ((const float2*)r1)[j2];
            nbs2[(2*j2    )*32 + rp] = pack2(a.x, bb.x);
            nbs2[(2*j2 + 1)*32 + rp] = pack2(a.y, bb.y);
        }
        __syncthreads();

        const float* wbase = g_WoT + (size_t)(ch*130)*Cc;
        #pragma unroll 2
        for (int jj = 0; jj < 130; jj++) {
            float4 w = ((const float4*)(wbase + jj*Cc))[jg];
            u64 w0 = dup2(w.x), w1 = dup2(w.y), w2 = dup2(w.z), w3 = dup2(w.w);
            ulonglong2 xa = *((const ulonglong2*)&nbs2[jj*32 + rpg*4]);
            ulonglong2 xb = *((const ulonglong2*)&nbs2[jj*32 + rpg*4 + 2]);
            u64 xv[4] = {xa.x, xa.y, xb.x, xb.y};
            #pragma unroll
            for (int r = 0; r < 4; r++) {
                fma2(acc[r][0], xv[r], w0);
                fma2(acc[r][1], xv[r], w1);
                fma2(acc[r][2], xv[r], w2);
                fma2(acc[r][3], xv[r], w3);
            }
        }
    }

    float4 bias = ((const float4*)bp)[jg];
    #pragma unroll
    for (int r = 0; r < 4; r++) {
        int rp = rpg*4 + r;
        float lo0, hi0, lo1, hi1, lo2, hi2, lo3, hi3;
        unpack2(acc[r][0], lo0, hi0);
        unpack2(acc[r][1], lo1, hi1);
        unpack2(acc[r][2], lo2, hi2);
        unpack2(acc[r][3], lo3, hi3);
        int s = s0 + 2*rp;
        float4 vlo = make_float4(lo0 + bias.x, lo1 + bias.y, lo2 + bias.z, lo3 + bias.w);
        float4 vhi = make_float4(hi0 + bias.x, hi1 + bias.y, hi2 + bias.z, hi3 + bias.w);
        ((float4*)(out + ((size_t)((b*Sc + s    )*Tc + t))*Cc))[jg] = vlo;
        ((float4*)(out + ((size_t)((b*Sc + s + 1)*Tc + t))*Cc))[jg] = vhi;
    }
}

// ---------------------------------------------------------------------------
extern "C" void kernel_launch(void* const* d_in, const int* in_sizes, int n_in,
                              void* d_out, int out_size) {
    const float* x    = (const float*)d_in[0];
    const void*  sidx = d_in[1];
    const float* swgt = (const float*)d_in[2];
    const float* ali  = (const float*)d_in[3];
    const float* dstp = (const float*)d_in[4];
    const float* Wq   = (const float*)d_in[5];
    const float* Wk   = (const float*)d_in[6];
    const float* Wv   = (const float*)d_in[7];
    const float* Wp   = (const float*)d_in[8];
    const float* bp   = (const float*)d_in[9];
    float* out = (float*)d_out;

    k_detect<<<1, 256>>>((const unsigned int*)sidx);
    k0_combine<<<(Cc*Uc + 255)/256, 256>>>(Wq, Wk, Wv, Wp);
    k1_u<<<Nc/32, 544>>>(x);
    k2_attn<<<Nc, 128>>>(x, sidx, swgt, ali, dstp);
    k3_out<<<Nc/64, 256>>>(bp, out);
}

// round 4
// speedup vs baseline: 2.0653x; 2.0653x over previous
#include <cuda_runtime.h>
#include <math.h>

#define Bc 2
#define Sc 2048
#define Tc 8
#define Cc 128
#define Kc 16
#define Hc 4
#define Dc 32
#define Fc 130        // C+2
#define F2c 132
#define BTc (Bc*Tc)   // 16
#define Nc (BTc*Sc)   // 32768
#define Uc 520        // H*(C+2)
#define UP 528        // padded row stride for U/NB (66 n8-tiles)

typedef unsigned int u32;

// ---- scratch (__device__ globals; no allocations allowed) ----
__device__ float g_Wu[Cc*UP];             // [c][j] tf32 bits, pad j>=520 zero
__device__ float g_WoT[UP*Cc];            // [j][c'] tf32 bits, pad rows zero
__device__ float g_U[(size_t)Nc*UP];      // 69 MB
__device__ float g_NB[(size_t)Nc*UP];     // 69 MB
__device__ int   g_is64;

__device__ __forceinline__ u32 tf32_of(float f) {
    u32 u;
    asm("cvt.rna.tf32.f32 %0, %1;" : "=r"(u) : "f"(f));
    return u;
}
__device__ __forceinline__ void mma_tf32(float* d, u32 a0, u32 a1, u32 a2, u32 a3,
                                         u32 b0, u32 b1) {
    asm("mma.sync.aligned.m16n8k8.row.col.f32.tf32.tf32.f32 "
        "{%0,%1,%2,%3}, {%4,%5,%6,%7}, {%8,%9}, {%0,%1,%2,%3};"
        : "+f"(d[0]), "+f"(d[1]), "+f"(d[2]), "+f"(d[3])
        : "r"(a0), "r"(a1), "r"(a2), "r"(a3), "r"(b0), "r"(b1));
}

// ---------------------------------------------------------------------------
__global__ void k_detect(const unsigned int* __restrict__ p) {
    __shared__ int any;
    if (threadIdx.x == 0) any = 0;
    __syncthreads();
    for (int i = threadIdx.x; i < 4096; i += blockDim.x)
        if (p[2*i + 1] != 0u) any = 1;
    __syncthreads();
    if (threadIdx.x == 0) g_is64 = (any == 0) ? 1 : 0;
}

// ---------------------------------------------------------------------------
// k0: combined weights, tf32-rounded, padded with zeros.
// ---------------------------------------------------------------------------
__global__ void k0_combine(const float* __restrict__ Wq, const float* __restrict__ Wk,
                           const float* __restrict__ Wv, const float* __restrict__ Wp) {
    int i = blockIdx.x * blockDim.x + threadIdx.x;
    if (i >= Cc*UP) return;
    int c = i / UP;
    int j = i % UP;
    float su = 0.f, so = 0.f;
    if (j < Uc) {
        int h = j / Fc;
        int f = j % Fc;
        #pragma unroll
        for (int d = 0; d < Dc; d++) {
            int hd = h*Dc + d;
            su = fmaf(Wq[hd*Cc + c], Wk[hd*(Cc+2) + f], su);
            so = fmaf(Wp[c*Cc + hd], Wv[hd*(Cc+2) + f], so);
        }
        su *= rsqrtf((float)Dc);
    }
    g_Wu[c*UP + j]  = __uint_as_float(tf32_of(su));
    g_WoT[j*Cc + c] = __uint_as_float(tf32_of(so));
}

// ---------------------------------------------------------------------------
// k1: U = X_ @ W_u via tf32 MMA. 128 rows/block, 256 threads (8 warps),
// warp w owns m16 tile [16w,16w+16). n chunked: 8x64 + 16. k = 128 (16 steps).
// smem: xs 128x132 (stride 4 mod 32) + ws 128x72 (stride 8 mod 32).
// ---------------------------------------------------------------------------
__global__ __launch_bounds__(256) void k1_u(const float* __restrict__ x) {
    extern __shared__ u32 sm1[];
    u32* xs = sm1;                 // 128*132
    u32* ws = sm1 + 128*132;       // 128*72
    int base = blockIdx.x * 128;
    int bt = base >> 11;
    int s0 = base & 2047;
    int b = bt >> 3, t = bt & 7;
    int tid = threadIdx.x;
    int wid = tid >> 5, lane = tid & 31, gid = lane >> 2, tig = lane & 3;
    int m0 = wid * 16;

    // stage x tile (tf32-converted)
    for (int idx = tid; idx < 4096; idx += 256) {
        int r = idx >> 5, c4 = idx & 31;
        float4 v = ((const float4*)(x + ((size_t)((b*Sc + s0 + r)*Tc + t))*Cc))[c4];
        u32 w0 = tf32_of(v.x), w1 = tf32_of(v.y), w2 = tf32_of(v.z), w3 = tf32_of(v.w);
        uint4 u = make_uint4(w0, w1, w2, w3);
        *((uint4*)&xs[r*132 + c4*4]) = u;
    }
    __syncthreads();

    int rowA0 = (m0 + gid) * 132;
    int rowA1 = (m0 + gid + 8) * 132;

    for (int ch = 0; ch < 9; ch++) {
        int j0 = ch * 64;
        int jtn = (ch < 8) ? 8 : 2;
        int jw4 = jtn * 2;           // jw/4
        if (ch) __syncthreads();
        // stage Wu chunk [128][jw]
        for (int idx = tid; idx < 128*jw4; idx += 256) {
            int c = idx / jw4, q = idx - c*jw4;
            uint4 w = ((const uint4*)(g_Wu + (size_t)c*UP + j0))[q];
            *((uint4*)&ws[c*72 + q*4]) = w;
        }
        __syncthreads();

        float acc[8][4];
        #pragma unroll
        for (int jt = 0; jt < 8; jt++)
            #pragma unroll
            for (int e = 0; e < 4; e++) acc[jt][e] = 0.f;

        #pragma unroll
        for (int ks = 0; ks < 16; ks++) {
            int kk = ks * 8;
            u32 a0 = xs[rowA0 + kk + tig];
            u32 a1 = xs[rowA1 + kk + tig];
            u32 a2 = xs[rowA0 + kk + tig + 4];
            u32 a3 = xs[rowA1 + kk + tig + 4];
            const u32* w0p = &ws[(kk + tig)*72 + gid];
            const u32* w1p = &ws[(kk + tig + 4)*72 + gid];
            #pragma unroll
            for (int jt = 0; jt < 8; jt++) {
                if (jt < jtn) {
                    u32 b0 = w0p[jt*8];
                    u32 b1 = w1p[jt*8];
                    mma_tf32(acc[jt], a0, a1, a2, a3, b0, b1);
                }
            }
        }
        #pragma unroll
        for (int jt = 0; jt < 8; jt++) {
            if (jt < jtn) {
                int j = j0 + jt*8 + 2*tig;
                float2 lo = make_float2(acc[jt][0], acc[jt][1]);
                float2 hi = make_float2(acc[jt][2], acc[jt][3]);
                *((float2*)(g_U + (size_t)(base + m0 + gid    )*UP + j)) = lo;
                *((float2*)(g_U + (size_t)(base + m0 + gid + 8)*UP + j)) = hi;
            }
        }
    }
}

// ---------------------------------------------------------------------------
// k2: per (bt,s): gather K neighbors, logits, softmax, weighted neighbor sum.
// (round-2 version; U/NB row stride UP, NB pad cols zeroed)
// ---------------------------------------------------------------------------
__global__ __launch_bounds__(128) void k2_attn(const float* __restrict__ x,
                                               const void* __restrict__ sidx,
                                               const float* __restrict__ swgt,
                                               const float* __restrict__ ali,
                                               const float* __restrict__ dstp) {
    __shared__ __align__(16) float nb[Kc][F2c];
    __shared__ __align__(16) float us[Uc];
    __shared__ float lg[Hc][Kc];
    __shared__ float attn_s[Hc][Kc];

    int n = blockIdx.x;
    int bt = n >> 11;
    int b = bt >> 3, t = bt & 7;
    int tid = threadIdx.x;

    for (int i = tid; i < Uc/4; i += 128)
        ((float4*)us)[i] = ((const float4*)(g_U + (size_t)n*UP))[i];

    int k = tid >> 3, l8 = tid & 7;
    long long jn;
    if (g_is64) jn = ((const long long*)sidx)[(size_t)n*Kc + k];
    else        jn = (long long)((const int*)sidx)[(size_t)n*Kc + k];
    const float4* src = (const float4*)(x + ((size_t)((b*Sc + (int)jn)*Tc + t)) * Cc);
    #pragma unroll
    for (int q = 0; q < 4; q++) {
        int f4 = l8 + q*8;
        *((float4*)&nb[k][f4*4]) = src[f4];
    }
    if (l8 == 0) {
        nb[k][128] = ali [(size_t)n*Kc + k];
        nb[k][129] = dstp[(size_t)n*Kc + k];
    }
    __syncthreads();

    {
        float p0 = 0.f, p1 = 0.f, p2 = 0.f, p3 = 0.f;
        #pragma unroll 4
        for (int f = l8; f < Fc; f += 8) {
            float v = nb[k][f];
            p0 = fmaf(us[0*Fc + f], v, p0);
            p1 = fmaf(us[1*Fc + f], v, p1);
            p2 = fmaf(us[2*Fc + f], v, p2);
            p3 = fmaf(us[3*Fc + f], v, p3);
        }
        #pragma unroll
        for (int o = 4; o >= 1; o >>= 1) {
            p0 += __shfl_xor_sync(0xffffffffu, p0, o, 8);
            p1 += __shfl_xor_sync(0xffffffffu, p1, o, 8);
            p2 += __shfl_xor_sync(0xffffffffu, p2, o, 8);
            p3 += __shfl_xor_sync(0xffffffffu, p3, o, 8);
        }
        if (l8 == 0) { lg[0][k] = p0; lg[1][k] = p1; lg[2][k] = p2; lg[3][k] = p3; }
    }
    __syncthreads();

    if (tid < Hc*Kc) {
        int h = tid >> 4, kk = tid & 15;
        float lgv = lg[h][kk] + __logf(swgt[(size_t)n*Kc + kk] + 1e-6f);
        float m = lgv;
        #pragma unroll
        for (int o = 8; o >= 1; o >>= 1)
            m = fmaxf(m, __shfl_xor_sync(0xffffffffu, m, o, 16));
        float e = __expf(lgv - m);
        float ssum = e;
        #pragma unroll
        for (int o = 8; o >= 1; o >>= 1)
            ssum += __shfl_xor_sync(0xffffffffu, ssum, o, 16);
        attn_s[h][kk] = e / ssum;
    }
    __syncthreads();

    float* dst = g_NB + (size_t)n*UP;
    for (int f = tid; f < Fc; f += 128) {
        float a0 = 0.f, a1 = 0.f, a2 = 0.f, a3 = 0.f;
        #pragma unroll
        for (int kk = 0; kk < Kc; kk++) {
            float v = nb[kk][f];
            a0 = fmaf(attn_s[0][kk], v, a0);
            a1 = fmaf(attn_s[1][kk], v, a1);
            a2 = fmaf(attn_s[2][kk], v, a2);
            a3 = fmaf(attn_s[3][kk], v, a3);
        }
        dst[0*Fc + f] = a0;
        dst[1*Fc + f] = a1;
        dst[2*Fc + f] = a2;
        dst[3*Fc + f] = a3;
    }
    if (tid < 8) dst[Uc + tid] = 0.f;   // zero pad cols 520..527
}

// ---------------------------------------------------------------------------
// k3: OUT = NB @ W_oT + bp via tf32 MMA. 128 rows/block, 256 threads.
// k = 528 chunked 6x88 (11 k-steps each); n = 128 (16 jt per warp).
// smem: as 128x100 (stride 4 mod 32) + ws 88x136 (stride 8 mod 32).
// ---------------------------------------------------------------------------
__global__ __launch_bounds__(256) void k3_out(const float* __restrict__ bp,
                                              float* __restrict__ out) {
    extern __shared__ u32 sm3[];
    u32* as3 = sm3;                // 128*100
    u32* ws3 = sm3 + 128*100;      // 88*136
    int base = blockIdx.x * 128;
    int bt = base >> 11;
    int s0 = base & 2047;
    int b = bt >> 3, t = bt & 7;
    int tid = threadIdx.x;
    int wid = tid >> 5, lane = tid & 31, gid = lane >> 2, tig = lane & 3;
    int m0 = wid * 16;
    int rowA0 = (m0 + gid) * 100;
    int rowA1 = (m0 + gid + 8) * 100;

    float acc[16][4];
    #pragma unroll
    for (int jt = 0; jt < 16; jt++)
        #pragma unroll
        for (int e = 0; e < 4; e++) acc[jt][e] = 0.f;

    for (int ch = 0; ch < 6; ch++) {
        if (ch) __syncthreads();
        // stage NB chunk [128][88] (tf32-converted)
        for (int idx = tid; idx < 128*22; idx += 256) {
            int r = idx / 22, q = idx - r*22;
            float4 v = ((const float4*)(g_NB + (size_t)(base + r)*UP + ch*88))[q];
            uint4 u = make_uint4(tf32_of(v.x), tf32_of(v.y), tf32_of(v.z), tf32_of(v.w));
            *((uint4*)&as3[r*100 + q*4]) = u;
        }
        // stage WoT chunk [88][128] (already tf32 bits)
        for (int idx = tid; idx < 88*32; idx += 256) {
            int kk = idx >> 5, q = idx & 31;
            uint4 w = ((const uint4*)(g_WoT + (size_t)(ch*88 + kk)*Cc))[q];
            *((uint4*)&ws3[kk*136 + q*4]) = w;
        }
        __syncthreads();

        #pragma unroll
        for (int ks = 0; ks < 11; ks++) {
            int kk = ks * 8;
            u32 a0 = as3[rowA0 + kk + tig];
            u32 a1 = as3[rowA1 + kk + tig];
            u32 a2 = as3[rowA0 + kk + tig + 4];
            u32 a3 = as3[rowA1 + kk + tig + 4];
            const u32* w0p = &ws3[(kk + tig)*136 + gid];
            const u32* w1p = &ws3[(kk + tig + 4)*136 + gid];
            #pragma unroll
            for (int jt = 0; jt < 16; jt++) {
                u32 b0 = w0p[jt*8];
                u32 b1 = w1p[jt*8];
                mma_tf32(acc[jt], a0, a1, a2, a3, b0, b1);
            }
        }
    }

    #pragma unroll
    for (int jt = 0; jt < 16; jt++) {
        int cp = jt*8 + 2*tig;
        float2 bv = *((const float2*)&bp[cp]);
        int sA = s0 + m0 + gid;
        int sB = sA + 8;
        float2 lo = make_float2(acc[jt][0] + bv.x, acc[jt][1] + bv.y);
        float2 hi = make_float2(acc[jt][2] + bv.x, acc[jt][3] + bv.y);
        *((float2*)(out + ((size_t)((b*Sc + sA)*Tc + t))*Cc + cp)) = lo;
        *((float2*)(out + ((size_t)((b*Sc + sB)*Tc + t))*Cc + cp)) = hi;
    }
}

// ---------------------------------------------------------------------------
extern "C" void kernel_launch(void* const* d_in, const int* in_sizes, int n_in,
                              void* d_out, int out_size) {
    const float* x    = (const float*)d_in[0];
    const void*  sidx = d_in[1];
    const float* swgt = (const float*)d_in[2];
    const float* ali  = (const float*)d_in[3];
    const float* dstp = (const float*)d_in[4];
    const float* Wq   = (const float*)d_in[5];
    const float* Wk   = (const float*)d_in[6];
    const float* Wv   = (const float*)d_in[7];
    const float* Wp   = (const float*)d_in[8];
    const float* bp   = (const float*)d_in[9];
    float* out = (float*)d_out;

    const int SM1 = (128*132 + 128*72) * 4;   // 104448
    const int SM3 = (128*100 + 88*136) * 4;   //  99072
    cudaFuncSetAttribute(k1_u,  cudaFuncAttributeMaxDynamicSharedMemorySize, SM1);
    cudaFuncSetAttribute(k3_out, cudaFuncAttributeMaxDynamicSharedMemorySize, SM3);

    k_detect<<<1, 256>>>((const unsigned int*)sidx);
    k0_combine<<<(Cc*UP + 255)/256, 256>>>(Wq, Wk, Wv, Wp);
    k1_u<<<Nc/128, 256, SM1>>>(x);
    k2_attn<<<Nc, 128>>>(x, sidx, swgt, ali, dstp);
    k3_out<<<Nc/128, 256, SM3>>>(bp, out);
}

// round 5
// speedup vs baseline: 2.1267x; 1.0297x over previous
#include <cuda_runtime.h>
#include <math.h>

#define Bc 2
#define Sc 2048
#define Tc 8
#define Cc 128
#define Kc 16
#define Hc 4
#define Dc 32
#define Fc 130        // C+2
#define BTc (Bc*Tc)   // 16
#define Nc (BTc*Sc)   // 32768
#define Uc 520        // H*(C+2)
#define UP 528        // padded row stride for U/NB

typedef unsigned int u32;

// ---- scratch (__device__ globals; no allocations allowed) ----
__device__ float g_Wu[Cc*UP];             // [c][j] tf32 bits, pad j>=520 zero
__device__ float g_WoT[UP*Cc];            // [j][c'] tf32 bits, pad rows zero
__device__ float g_U[(size_t)Nc*UP];      // fp32
__device__ float g_NB[(size_t)Nc*UP];     // tf32 bits (written by k2)
__device__ int   g_is64;

__device__ __forceinline__ u32 tf32_of(float f) {
    u32 u;
    asm("cvt.rna.tf32.f32 %0, %1;" : "=r"(u) : "f"(f));
    return u;
}
__device__ __forceinline__ void mma_tf32(float* d, u32 a0, u32 a1, u32 a2, u32 a3,
                                         u32 b0, u32 b1) {
    asm("mma.sync.aligned.m16n8k8.row.col.f32.tf32.tf32.f32 "
        "{%0,%1,%2,%3}, {%4,%5,%6,%7}, {%8,%9}, {%0,%1,%2,%3};"
        : "+f"(d[0]), "+f"(d[1]), "+f"(d[2]), "+f"(d[3])
        : "r"(a0), "r"(a1), "r"(a2), "r"(a3), "r"(b0), "r"(b1));
}

// ---------------------------------------------------------------------------
__global__ void k_detect(const unsigned int* __restrict__ p) {
    __shared__ int any;
    if (threadIdx.x == 0) any = 0;
    __syncthreads();
    for (int i = threadIdx.x; i < 4096; i += blockDim.x)
        if (p[2*i + 1] != 0u) any = 1;
    __syncthreads();
    if (threadIdx.x == 0) g_is64 = (any == 0) ? 1 : 0;
}

// ---------------------------------------------------------------------------
// k0: combined weights, tf32-rounded, padded with zeros.
// ---------------------------------------------------------------------------
__global__ void k0_combine(const float* __restrict__ Wq, const float* __restrict__ Wk,
                           const float* __restrict__ Wv, const float* __restrict__ Wp) {
    int i = blockIdx.x * blockDim.x + threadIdx.x;
    if (i >= Cc*UP) return;
    int c = i / UP;
    int j = i % UP;
    float su = 0.f, so = 0.f;
    if (j < Uc) {
        int h = j / Fc;
        int f = j % Fc;
        #pragma unroll
        for (int d = 0; d < Dc; d++) {
            int hd = h*Dc + d;
            su = fmaf(Wq[hd*Cc + c], Wk[hd*(Cc+2) + f], su);
            so = fmaf(Wp[c*Cc + hd], Wv[hd*(Cc+2) + f], so);
        }
        su *= rsqrtf((float)Dc);
    }
    g_Wu[c*UP + j]  = __uint_as_float(tf32_of(su));
    g_WoT[j*Cc + c] = __uint_as_float(tf32_of(so));
}

// ---------------------------------------------------------------------------
// k1: U = X_ @ W_u via tf32 MMA (unchanged from R4).
// ---------------------------------------------------------------------------
__global__ __launch_bounds__(256) void k1_u(const float* __restrict__ x) {
    extern __shared__ u32 sm1[];
    u32* xs = sm1;                 // 128*132
    u32* ws = sm1 + 128*132;       // 128*72
    int base = blockIdx.x * 128;
    int bt = base >> 11;
    int s0 = base & 2047;
    int b = bt >> 3, t = bt & 7;
    int tid = threadIdx.x;
    int wid = tid >> 5, lane = tid & 31, gid = lane >> 2, tig = lane & 3;
    int m0 = wid * 16;

    for (int idx = tid; idx < 4096; idx += 256) {
        int r = idx >> 5, c4 = idx & 31;
        float4 v = ((const float4*)(x + ((size_t)((b*Sc + s0 + r)*Tc + t))*Cc))[c4];
        uint4 u = make_uint4(tf32_of(v.x), tf32_of(v.y), tf32_of(v.z), tf32_of(v.w));
        *((uint4*)&xs[r*132 + c4*4]) = u;
    }
    __syncthreads();

    int rowA0 = (m0 + gid) * 132;
    int rowA1 = (m0 + gid + 8) * 132;

    for (int ch = 0; ch < 9; ch++) {
        int j0 = ch * 64;
        int jtn = (ch < 8) ? 8 : 2;
        int jw4 = jtn * 2;
        if (ch) __syncthreads();
        for (int idx = tid; idx < 128*jw4; idx += 256) {
            int c = idx / jw4, q = idx - c*jw4;
            uint4 w = ((const uint4*)(g_Wu + (size_t)c*UP + j0))[q];
            *((uint4*)&ws[c*72 + q*4]) = w;
        }
        __syncthreads();

        float acc[8][4];
        #pragma unroll
        for (int jt = 0; jt < 8; jt++)
            #pragma unroll
            for (int e = 0; e < 4; e++) acc[jt][e] = 0.f;

        #pragma unroll
        for (int ks = 0; ks < 16; ks++) {
            int kk = ks * 8;
            u32 a0 = xs[rowA0 + kk + tig];
            u32 a1 = xs[rowA1 + kk + tig];
            u32 a2 = xs[rowA0 + kk + tig + 4];
            u32 a3 = xs[rowA1 + kk + tig + 4];
            const u32* w0p = &ws[(kk + tig)*72 + gid];
            const u32* w1p = &ws[(kk + tig + 4)*72 + gid];
            #pragma unroll
            for (int jt = 0; jt < 8; jt++) {
                if (jt < jtn) {
                    mma_tf32(acc[jt], a0, a1, a2, a3, w0p[jt*8], w1p[jt*8]);
                }
            }
        }
        #pragma unroll
        for (int jt = 0; jt < 8; jt++) {
            if (jt < jtn) {
                int j = j0 + jt*8 + 2*tig;
                *((float2*)(g_U + (size_t)(base + m0 + gid    )*UP + j)) =
                    make_float2(acc[jt][0], acc[jt][1]);
                *((float2*)(g_U + (size_t)(base + m0 + gid + 8)*UP + j)) =
                    make_float2(acc[jt][2], acc[jt][3]);
            }
        }
    }
}

// ---------------------------------------------------------------------------
// k2: warp-autonomous attention. One warp per n, 4 n per 128-thread block.
// No __syncthreads — all phases warp-local. Writes NB as tf32 bits.
// ---------------------------------------------------------------------------
__global__ __launch_bounds__(128) void k2_attn(const float* __restrict__ x,
                                               const void* __restrict__ sidx,
                                               const float* __restrict__ swgt,
                                               const float* __restrict__ ali,
                                               const float* __restrict__ dstp) {
    __shared__ __align__(16) float nb[4][Kc][132];    // 33.8 KB (pads zeroed)
    __shared__ __align__(16) float us[4][Hc][132];    // 8.4 KB  (pads zeroed)
    __shared__ __align__(16) float attn_s[4][Kc][4];  // [k][h] packed float4
    __shared__ float lg[4][Hc][Kc];
    __shared__ float logw[4][Kc];

    int tid = threadIdx.x;
    int n4 = tid >> 5, lane = tid & 31;
    int n = blockIdx.x * 4 + n4;
    int bt = n >> 11;
    int b = bt >> 3, t = bt & 7;
    int k = lane >> 1, half = lane & 1;

    // ---- P0: gather neighbors (2 lanes per k, 16 float4 each) ----
    long long jn;
    if (g_is64) jn = ((const long long*)sidx)[(size_t)n*Kc + k];
    else        jn = (long long)((const int*)sidx)[(size_t)n*Kc + k];
    const float4* src = (const float4*)(x + ((size_t)((b*Sc + (int)jn)*Tc + t)) * Cc);
    {
        int f40 = half * 16;
        #pragma unroll
        for (int q = 0; q < 16; q++)
            *((float4*)&nb[n4][k][(f40 + q)*4]) = src[f40 + q];
    }
    if (half == 0) {
        nb[n4][k][128] = ali [(size_t)n*Kc + k];
        nb[n4][k][129] = dstp[(size_t)n*Kc + k];
    } else {
        nb[n4][k][130] = 0.f;
        nb[n4][k][131] = 0.f;
    }
    // u row -> us[h][f] (warp-local, lane-strided)
    {
        const float4* U4 = (const float4*)(g_U + (size_t)n*UP);
        for (int i4 = lane; i4 < 130; i4 += 32) {
            float4 v = U4[i4];
            int j = 4*i4;
            float arr[4] = {v.x, v.y, v.z, v.w};
            #pragma unroll
            for (int e = 0; e < 4; e++) {
                int jj = j + e;
                int h = jj / Fc;
                us[n4][h][jj - h*Fc] = arr[e];
            }
        }
        if (lane < 8) us[n4][lane >> 1][130 + (lane & 1)] = 0.f;
    }
    if (lane < Kc)
        logw[n4][lane] = __logf(swgt[(size_t)n*Kc + lane] + 1e-6f);
    __syncwarp();

    // ---- P1: logits (float4 over f, half splits f-range, 4 heads) ----
    {
        const float4* nb4 = (const float4*)&nb[n4][k][0];
        const float4* u0p = (const float4*)&us[n4][0][0];
        const float4* u1p = (const float4*)&us[n4][1][0];
        const float4* u2p = (const float4*)&us[n4][2][0];
        const float4* u3p = (const float4*)&us[n4][3][0];
        float p0 = 0.f, p1 = 0.f, p2 = 0.f, p3 = 0.f;
        int q0 = half ? 17 : 0;
        int qn = half ? 33 : 17;
        for (int q = q0; q < qn; q++) {
            float4 v = nb4[q];
            float4 a = u0p[q], bb = u1p[q], c = u2p[q], d = u3p[q];
            p0 = fmaf(a.x,v.x,fmaf(a.y,v.y,fmaf(a.z,v.z,fmaf(a.w,v.w,p0))));
            p1 = fmaf(bb.x,v.x,fmaf(bb.y,v.y,fmaf(bb.z,v.z,fmaf(bb.w,v.w,p1))));
            p2 = fmaf(c.x,v.x,fmaf(c.y,v.y,fmaf(c.z,v.z,fmaf(c.w,v.w,p2))));
            p3 = fmaf(d.x,v.x,fmaf(d.y,v.y,fmaf(d.z,v.z,fmaf(d.w,v.w,p3))));
        }
        p0 += __shfl_xor_sync(0xffffffffu, p0, 1);
        p1 += __shfl_xor_sync(0xffffffffu, p1, 1);
        p2 += __shfl_xor_sync(0xffffffffu, p2, 1);
        p3 += __shfl_xor_sync(0xffffffffu, p3, 1);
        float lw = logw[n4][k];
        if (half == 0) { lg[n4][0][k] = p0 + lw; lg[n4][1][k] = p1 + lw; }
        else           { lg[n4][2][k] = p2 + lw; lg[n4][3][k] = p3 + lw; }
    }
    __syncwarp();

    // ---- P2: softmax over k (warp-local; lanes 0-15 h, 16-31 h+1) ----
    #pragma unroll
    for (int e = 0; e < 2; e++) {
        int h = (lane >> 4) + 2*e;
        int kk = lane & 15;
        float lgv = lg[n4][h][kk];
        float m = lgv;
        #pragma unroll
        for (int o = 8; o >= 1; o >>= 1)
            m = fmaxf(m, __shfl_xor_sync(0xffffffffu, m, o, 16));
        float ex = __expf(lgv - m);
        float ssum = ex;
        #pragma unroll
        for (int o = 8; o >= 1; o >>= 1)
            ssum += __shfl_xor_sync(0xffffffffu, ssum, o, 16);
        attn_s[n4][kk][h] = ex / ssum;
    }
    __syncwarp();

    // ---- P3: nbar; lane = f0, 4+1 f-slots, attn via broadcast LDS.128 ----
    {
        float4 acc[4];
        float2 acct = make_float2(0.f, 0.f);  // tail holder (f=128+f0 for f0<2)
        float4 acc4t = make_float4(0.f,0.f,0.f,0.f);
        #pragma unroll
        for (int q = 0; q < 4; q++) acc[q] = make_float4(0.f,0.f,0.f,0.f);
        #pragma unroll
        for (int kk = 0; kk < Kc; kk++) {
            float4 a = *((const float4*)&attn_s[n4][kk][0]);
            const float* nbr = &nb[n4][kk][0];
            #pragma unroll
            for (int q = 0; q < 4; q++) {
                float v = nbr[lane + 32*q];
                acc[q].x = fmaf(a.x, v, acc[q].x);
                acc[q].y = fmaf(a.y, v, acc[q].y);
                acc[q].z = fmaf(a.z, v, acc[q].z);
                acc[q].w = fmaf(a.w, v, acc[q].w);
            }
            if (lane < 2) {
                float v = nbr[128 + lane];
                acc4t.x = fmaf(a.x, v, acc4t.x);
                acc4t.y = fmaf(a.y, v, acc4t.y);
                acc4t.z = fmaf(a.z, v, acc4t.z);
                acc4t.w = fmaf(a.w, v, acc4t.w);
            }
        }
        (void)acct;
        u32* dst = (u32*)(g_NB + (size_t)n*UP);
        #pragma unroll
        for (int q = 0; q < 4; q++) {
            int f = lane + 32*q;
            dst[0*Fc + f] = tf32_of(acc[q].x);
            dst[1*Fc + f] = tf32_of(acc[q].y);
            dst[2*Fc + f] = tf32_of(acc[q].z);
            dst[3*Fc + f] = tf32_of(acc[q].w);
        }
        if (lane < 2) {
            int f = 128 + lane;
            dst[0*Fc + f] = tf32_of(acc4t.x);
            dst[1*Fc + f] = tf32_of(acc4t.y);
            dst[2*Fc + f] = tf32_of(acc4t.z);
            dst[3*Fc + f] = tf32_of(acc4t.w);
        }
        if (lane < 8) dst[Uc + lane] = 0u;   // zero pad cols
    }
}

// ---------------------------------------------------------------------------
// k3: OUT = NB @ W_oT + bp via tf32 MMA. NB already tf32 bits — no cvt.
// ---------------------------------------------------------------------------
__global__ __launch_bounds__(256) void k3_out(const float* __restrict__ bp,
                                              float* __restrict__ out) {
    extern __shared__ u32 sm3[];
    u32* as3 = sm3;                // 128*100
    u32* ws3 = sm3 + 128*100;      // 88*136
    int base = blockIdx.x * 128;
    int bt = base >> 11;
    int s0 = base & 2047;
    int b = bt >> 3, t = bt & 7;
    int tid = threadIdx.x;
    int wid = tid >> 5, lane = tid & 31, gid = lane >> 2, tig = lane & 3;
    int m0 = wid * 16;
    int rowA0 = (m0 + gid) * 100;
    int rowA1 = (m0 + gid + 8) * 100;

    float acc[16][4];
    #pragma unroll
    for (int jt = 0; jt < 16; jt++)
        #pragma unroll
        for (int e = 0; e < 4; e++) acc[jt][e] = 0.f;

    for (int ch = 0; ch < 6; ch++) {
        if (ch) __syncthreads();
        for (int idx = tid; idx < 128*22; idx += 256) {
            int r = idx / 22, q = idx - r*22;
            uint4 v = ((const uint4*)(g_NB + (size_t)(base + r)*UP + ch*88))[q];
            *((uint4*)&as3[r*100 + q*4]) = v;
        }
        for (int idx = tid; idx < 88*32; idx += 256) {
            int kk = idx >> 5, q = idx & 31;
            uint4 w = ((const uint4*)(g_WoT + (size_t)(ch*88 + kk)*Cc))[q];
            *((uint4*)&ws3[kk*136 + q*4]) = w;
        }
        __syncthreads();

        #pragma unroll
        for (int ks = 0; ks < 11; ks++) {
            int kk = ks * 8;
            u32 a0 = as3[rowA0 + kk + tig];
            u32 a1 = as3[rowA1 + kk + tig];
            u32 a2 = as3[rowA0 + kk + tig + 4];
            u32 a3 = as3[rowA1 + kk + tig + 4];
            const u32* w0p = &ws3[(kk + tig)*136 + gid];
            const u32* w1p = &ws3[(kk + tig + 4)*136 + gid];
            #pragma unroll
            for (int jt = 0; jt < 16; jt++)
                mma_tf32(acc[jt], a0, a1, a2, a3, w0p[jt*8], w1p[jt*8]);
        }
    }

    #pragma unroll
    for (int jt = 0; jt < 16; jt++) {
        int cp = jt*8 + 2*tig;
        float2 bv = *((const float2*)&bp[cp]);
        int sA = s0 + m0 + gid;
        int sB = sA + 8;
        *((float2*)(out + ((size_t)((b*Sc + sA)*Tc + t))*Cc + cp)) =
            make_float2(acc[jt][0] + bv.x, acc[jt][1] + bv.y);
        *((float2*)(out + ((size_t)((b*Sc + sB)*Tc + t))*Cc + cp)) =
            make_float2(acc[jt][2] + bv.x, acc[jt][3] + bv.y);
    }
}

// ---------------------------------------------------------------------------
extern "C" void kernel_launch(void* const* d_in, const int* in_sizes, int n_in,
                              void* d_out, int out_size) {
    const float* x    = (const float*)d_in[0];
    const void*  sidx = d_in[1];
    const float* swgt = (const float*)d_in[2];
    const float* ali  = (const float*)d_in[3];
    const float* dstp = (const float*)d_in[4];
    const float* Wq   = (const float*)d_in[5];
    const float* Wk   = (const float*)d_in[6];
    const float* Wv   = (const float*)d_in[7];
    const float* Wp   = (const float*)d_in[8];
    const float* bp   = (const float*)d_in[9];
    float* out = (float*)d_out;

    const int SM1 = (128*132 + 128*72) * 4;
    const int SM3 = (128*100 + 88*136) * 4;
    cudaFuncSetAttribute(k1_u,   cudaFuncAttributeMaxDynamicSharedMemorySize, SM1);
    cudaFuncSetAttribute(k3_out, cudaFuncAttributeMaxDynamicSharedMemorySize, SM3);

    k_detect<<<1, 256>>>((const unsigned int*)sidx);
    k0_combine<<<(Cc*UP + 255)/256, 256>>>(Wq, Wk, Wv, Wp);
    k1_u<<<Nc/128, 256, SM1>>>(x);
    k2_attn<<<Nc/4, 128>>>(x, sidx, swgt, ali, dstp);
    k3_out<<<Nc/128, 256, SM3>>>(bp, out);
}

// round 6
// speedup vs baseline: 2.1922x; 1.0308x over previous
#include <cuda_runtime.h>
#include <math.h>

#define Bc 2
#define Sc 2048
#define Tc 8
#define Cc 128
#define Kc 16
#define Hc 4
#define Dc 32
#define Fc 130        // C+2
#define BTc (Bc*Tc)   // 16
#define Nc (BTc*Sc)   // 32768
#define Uc 520        // H*(C+2)
#define UP 528        // padded row stride for U/NB

typedef unsigned int u32;

// ---- scratch (__device__ globals; no allocations allowed) ----
__device__ float g_Wu[Cc*UP];             // [c][j] tf32 bits, pad j>=520 zero
__device__ float g_WoT[UP*Cc];            // [j][c'] tf32 bits, pad rows zero
__device__ float g_U[(size_t)Nc*UP];      // fp32
__device__ float g_NB[(size_t)Nc*UP];     // tf32 bits (written by k2)
__device__ int   g_is64;

__device__ __forceinline__ u32 tf32_of(float f) {
    u32 u;
    asm("cvt.rna.tf32.f32 %0, %1;" : "=r"(u) : "f"(f));
    return u;
}
__device__ __forceinline__ void mma_tf32(float* d, u32 a0, u32 a1, u32 a2, u32 a3,
                                         u32 b0, u32 b1) {
    asm("mma.sync.aligned.m16n8k8.row.col.f32.tf32.tf32.f32 "
        "{%0,%1,%2,%3}, {%4,%5,%6,%7}, {%8,%9}, {%0,%1,%2,%3};"
        : "+f"(d[0]), "+f"(d[1]), "+f"(d[2]), "+f"(d[3])
        : "r"(a0), "r"(a1), "r"(a2), "r"(a3), "r"(b0), "r"(b1));
}

// ---------------------------------------------------------------------------
__global__ void k_detect(const unsigned int* __restrict__ p) {
    __shared__ int any;
    if (threadIdx.x == 0) any = 0;
    __syncthreads();
    for (int i = threadIdx.x; i < 4096; i += blockDim.x)
        if (p[2*i + 1] != 0u) any = 1;
    __syncthreads();
    if (threadIdx.x == 0) g_is64 = (any == 0) ? 1 : 0;
}

// ---------------------------------------------------------------------------
// k0: combined weights, tf32-rounded, padded with zeros.
// ---------------------------------------------------------------------------
__global__ void k0_combine(const float* __restrict__ Wq, const float* __restrict__ Wk,
                           const float* __restrict__ Wv, const float* __restrict__ Wp) {
    int i = blockIdx.x * blockDim.x + threadIdx.x;
    if (i >= Cc*UP) return;
    int c = i / UP;
    int j = i % UP;
    float su = 0.f, so = 0.f;
    if (j < Uc) {
        int h = j / Fc;
        int f = j % Fc;
        #pragma unroll
        for (int d = 0; d < Dc; d++) {
            int hd = h*Dc + d;
            su = fmaf(Wq[hd*Cc + c], Wk[hd*(Cc+2) + f], su);
            so = fmaf(Wp[c*Cc + hd], Wv[hd*(Cc+2) + f], so);
        }
        su *= rsqrtf((float)Dc);
    }
    g_Wu[c*UP + j]  = __uint_as_float(tf32_of(su));
    g_WoT[j*Cc + c] = __uint_as_float(tf32_of(so));
}

// ---------------------------------------------------------------------------
// k1: U = X_ @ W_u via tf32 MMA (unchanged).
// ---------------------------------------------------------------------------
__global__ __launch_bounds__(256) void k1_u(const float* __restrict__ x) {
    extern __shared__ u32 sm1[];
    u32* xs = sm1;                 // 128*132
    u32* ws = sm1 + 128*132;       // 128*72
    int base = blockIdx.x * 128;
    int bt = base >> 11;
    int s0 = base & 2047;
    int b = bt >> 3, t = bt & 7;
    int tid = threadIdx.x;
    int wid = tid >> 5, lane = tid & 31, gid = lane >> 2, tig = lane & 3;
    int m0 = wid * 16;

    for (int idx = tid; idx < 4096; idx += 256) {
        int r = idx >> 5, c4 = idx & 31;
        float4 v = ((const float4*)(x + ((size_t)((b*Sc + s0 + r)*Tc + t))*Cc))[c4];
        uint4 u = make_uint4(tf32_of(v.x), tf32_of(v.y), tf32_of(v.z), tf32_of(v.w));
        *((uint4*)&xs[r*132 + c4*4]) = u;
    }
    __syncthreads();

    int rowA0 = (m0 + gid) * 132;
    int rowA1 = (m0 + gid + 8) * 132;

    for (int ch = 0; ch < 9; ch++) {
        int j0 = ch * 64;
        int jtn = (ch < 8) ? 8 : 2;
        int jw4 = jtn * 2;
        if (ch) __syncthreads();
        for (int idx = tid; idx < 128*jw4; idx += 256) {
            int c = idx / jw4, q = idx - c*jw4;
            uint4 w = ((const uint4*)(g_Wu + (size_t)c*UP + j0))[q];
            *((uint4*)&ws[c*72 + q*4]) = w;
        }
        __syncthreads();

        float acc[8][4];
        #pragma unroll
        for (int jt = 0; jt < 8; jt++)
            #pragma unroll
            for (int e = 0; e < 4; e++) acc[jt][e] = 0.f;

        #pragma unroll
        for (int ks = 0; ks < 16; ks++) {
            int kk = ks * 8;
            u32 a0 = xs[rowA0 + kk + tig];
            u32 a1 = xs[rowA1 + kk + tig];
            u32 a2 = xs[rowA0 + kk + tig + 4];
            u32 a3 = xs[rowA1 + kk + tig + 4];
            const u32* w0p = &ws[(kk + tig)*72 + gid];
            const u32* w1p = &ws[(kk + tig + 4)*72 + gid];
            #pragma unroll
            for (int jt = 0; jt < 8; jt++) {
                if (jt < jtn) {
                    mma_tf32(acc[jt], a0, a1, a2, a3, w0p[jt*8], w1p[jt*8]);
                }
            }
        }
        #pragma unroll
        for (int jt = 0; jt < 8; jt++) {
            if (jt < jtn) {
                int j = j0 + jt*8 + 2*tig;
                *((float2*)(g_U + (size_t)(base + m0 + gid    )*UP + j)) =
                    make_float2(acc[jt][0], acc[jt][1]);
                *((float2*)(g_U + (size_t)(base + m0 + gid + 8)*UP + j)) =
                    make_float2(acc[jt][2], acc[jt][3]);
            }
        }
    }
}

// ---------------------------------------------------------------------------
// k2: warp-autonomous attention; lane -> (k, half) = (lane&15, lane>>4)
// so every 8-lane issue phase spans 8 distinct nb rows => conflict-free
// LDS/STS.128 on nb. No __syncthreads. Writes NB as tf32 bits.
// ---------------------------------------------------------------------------
__global__ __launch_bounds__(128) void k2_attn(const float* __restrict__ x,
                                               const void* __restrict__ sidx,
                                               const float* __restrict__ swgt,
                                               const float* __restrict__ ali,
                                               const float* __restrict__ dstp) {
    __shared__ __align__(16) float nb[4][Kc][132];    // 33.8 KB
    __shared__ __align__(16) float us[4][Hc][132];    // 8.4 KB
    __shared__ __align__(16) float attn_s[4][Kc][4];  // [k][h] packed float4
    __shared__ float lg[4][Hc][Kc];
    __shared__ float logw[4][Kc];

    int tid = threadIdx.x;
    int n4 = tid >> 5, lane = tid & 31;
    int n = blockIdx.x * 4 + n4;
    int bt = n >> 11;
    int b = bt >> 3, t = bt & 7;
    int k = lane & 15, half = lane >> 4;          // conflict-free mapping

    // ---- P0: gather neighbors (2 lanes per k, 16 float4 each) ----
    long long jn;
    if (g_is64) jn = ((const long long*)sidx)[(size_t)n*Kc + k];
    else        jn = (long long)((const int*)sidx)[(size_t)n*Kc + k];
    const float4* src = (const float4*)(x + ((size_t)((b*Sc + (int)jn)*Tc + t)) * Cc);
    {
        int f40 = half * 16;
        #pragma unroll
        for (int q = 0; q < 16; q++)
            *((float4*)&nb[n4][k][(f40 + q)*4]) = src[f40 + q];
    }
    if (half == 0) {
        nb[n4][k][128] = ali [(size_t)n*Kc + k];
        nb[n4][k][129] = dstp[(size_t)n*Kc + k];
    } else {
        nb[n4][k][130] = 0.f;
        nb[n4][k][131] = 0.f;
    }
    // u row -> us[h][f] (warp-local, lane-strided)
    {
        const float4* U4 = (const float4*)(g_U + (size_t)n*UP);
        for (int i4 = lane; i4 < 130; i4 += 32) {
            float4 v = U4[i4];
            int j = 4*i4;
            float arr[4] = {v.x, v.y, v.z, v.w};
            #pragma unroll
            for (int e = 0; e < 4; e++) {
                int jj = j + e;
                int h = jj / Fc;
                us[n4][h][jj - h*Fc] = arr[e];
            }
        }
        if (lane < 8) us[n4][lane >> 1][130 + (lane & 1)] = 0.f;
    }
    if (lane < Kc)
        logw[n4][lane] = __logf(swgt[(size_t)n*Kc + lane] + 1e-6f);
    __syncwarp();

    // ---- P1: logits (float4 over f, half splits f-range, 4 heads) ----
    {
        const float4* nb4 = (const float4*)&nb[n4][k][0];
        const float4* u0p = (const float4*)&us[n4][0][0];
        const float4* u1p = (const float4*)&us[n4][1][0];
        const float4* u2p = (const float4*)&us[n4][2][0];
        const float4* u3p = (const float4*)&us[n4][3][0];
        float p0 = 0.f, p1 = 0.f, p2 = 0.f, p3 = 0.f;
        int q0 = half ? 17 : 0;
        int qn = half ? 33 : 17;
        for (int q = q0; q < qn; q++) {
            float4 v = nb4[q];
            float4 a = u0p[q], bb = u1p[q], c = u2p[q], d = u3p[q];
            p0 = fmaf(a.x,v.x,fmaf(a.y,v.y,fmaf(a.z,v.z,fmaf(a.w,v.w,p0))));
            p1 = fmaf(bb.x,v.x,fmaf(bb.y,v.y,fmaf(bb.z,v.z,fmaf(bb.w,v.w,p1))));
            p2 = fmaf(c.x,v.x,fmaf(c.y,v.y,fmaf(c.z,v.z,fmaf(c.w,v.w,p2))));
            p3 = fmaf(d.x,v.x,fmaf(d.y,v.y,fmaf(d.z,v.z,fmaf(d.w,v.w,p3))));
        }
        // combine the two f-halves: partner lane is lane ^ 16 (same k)
        p0 += __shfl_xor_sync(0xffffffffu, p0, 16);
        p1 += __shfl_xor_sync(0xffffffffu, p1, 16);
        p2 += __shfl_xor_sync(0xffffffffu, p2, 16);
        p3 += __shfl_xor_sync(0xffffffffu, p3, 16);
        float lw = logw[n4][k];
        if (half == 0) { lg[n4][0][k] = p0 + lw; lg[n4][1][k] = p1 + lw; }
        else           { lg[n4][2][k] = p2 + lw; lg[n4][3][k] = p3 + lw; }
    }
    __syncwarp();

    // ---- P2: softmax over k (lanes 0-15 h, 16-31 h+1; two passes) ----
    #pragma unroll
    for (int e = 0; e < 2; e++) {
        int h = (lane >> 4) + 2*e;
        int kk = lane & 15;
        float lgv = lg[n4][h][kk];
        float m = lgv;
        #pragma unroll
        for (int o = 8; o >= 1; o >>= 1)
            m = fmaxf(m, __shfl_xor_sync(0xffffffffu, m, o, 16));
        float ex = __expf(lgv - m);
        float ssum = ex;
        #pragma unroll
        for (int o = 8; o >= 1; o >>= 1)
            ssum += __shfl_xor_sync(0xffffffffu, ssum, o, 16);
        attn_s[n4][kk][h] = ex / ssum;
    }
    __syncwarp();

    // ---- P3: nbar; lane = f0, 4+tail f-slots, attn via broadcast LDS.128 ----
    {
        float4 acc[4];
        float4 acc4t = make_float4(0.f,0.f,0.f,0.f);
        #pragma unroll
        for (int q = 0; q < 4; q++) acc[q] = make_float4(0.f,0.f,0.f,0.f);
        #pragma unroll
        for (int kk = 0; kk < Kc; kk++) {
            float4 a = *((const float4*)&attn_s[n4][kk][0]);
            const float* nbr = &nb[n4][kk][0];
            #pragma unroll
            for (int q = 0; q < 4; q++) {
                float v = nbr[lane + 32*q];
                acc[q].x = fmaf(a.x, v, acc[q].x);
                acc[q].y = fmaf(a.y, v, acc[q].y);
                acc[q].z = fmaf(a.z, v, acc[q].z);
                acc[q].w = fmaf(a.w, v, acc[q].w);
            }
            if (lane < 2) {
                float v = nbr[128 + lane];
                acc4t.x = fmaf(a.x, v, acc4t.x);
                acc4t.y = fmaf(a.y, v, acc4t.y);
                acc4t.z = fmaf(a.z, v, acc4t.z);
                acc4t.w = fmaf(a.w, v, acc4t.w);
            }
        }
        u32* dst = (u32*)(g_NB + (size_t)n*UP);
        #pragma unroll
        for (int q = 0; q < 4; q++) {
            int f = lane + 32*q;
            dst[0*Fc + f] = tf32_of(acc[q].x);
            dst[1*Fc + f] = tf32_of(acc[q].y);
            dst[2*Fc + f] = tf32_of(acc[q].z);
            dst[3*Fc + f] = tf32_of(acc[q].w);
        }
        if (lane < 2) {
            int f = 128 + lane;
            dst[0*Fc + f] = tf32_of(acc4t.x);
            dst[1*Fc + f] = tf32_of(acc4t.y);
            dst[2*Fc + f] = tf32_of(acc4t.z);
            dst[3*Fc + f] = tf32_of(acc4t.w);
        }
        if (lane < 8) dst[Uc + lane] = 0u;   // zero pad cols
    }
}

// ---------------------------------------------------------------------------
// k3: OUT = NB @ W_oT + bp via tf32 MMA (unchanged).
// ---------------------------------------------------------------------------
__global__ __launch_bounds__(256) void k3_out(const float* __restrict__ bp,
                                              float* __restrict__ out) {
    extern __shared__ u32 sm3[];
    u32* as3 = sm3;                // 128*100
    u32* ws3 = sm3 + 128*100;      // 88*136
    int base = blockIdx.x * 128;
    int bt = base >> 11;
    int s0 = base & 2047;
    int b = bt >> 3, t = bt & 7;
    int tid = threadIdx.x;
    int wid = tid >> 5, lane = tid & 31, gid = lane >> 2, tig = lane & 3;
    int m0 = wid * 16;
    int rowA0 = (m0 + gid) * 100;
    int rowA1 = (m0 + gid + 8) * 100;

    float acc[16][4];
    #pragma unroll
    for (int jt = 0; jt < 16; jt++)
        #pragma unroll
        for (int e = 0; e < 4; e++) acc[jt][e] = 0.f;

    for (int ch = 0; ch < 6; ch++) {
        if (ch) __syncthreads();
        for (int idx = tid; idx < 128*22; idx += 256) {
            int r = idx / 22, q = idx - r*22;
            uint4 v = ((const uint4*)(g_NB + (size_t)(base + r)*UP + ch*88))[q];
            *((uint4*)&as3[r*100 + q*4]) = v;
        }
        for (int idx = tid; idx < 88*32; idx += 256) {
            int kk = idx >> 5, q = idx & 31;
            uint4 w = ((const uint4*)(g_WoT + (size_t)(ch*88 + kk)*Cc))[q];
            *((uint4*)&ws3[kk*136 + q*4]) = w;
        }
        __syncthreads();

        #pragma unroll
        for (int ks = 0; ks < 11; ks++) {
            int kk = ks * 8;
            u32 a0 = as3[rowA0 + kk + tig];
            u32 a1 = as3[rowA1 + kk + tig];
            u32 a2 = as3[rowA0 + kk + tig + 4];
            u32 a3 = as3[rowA1 + kk + tig + 4];
            const u32* w0p = &ws3[(kk + tig)*136 + gid];
            const u32* w1p = &ws3[(kk + tig + 4)*136 + gid];
            #pragma unroll
            for (int jt = 0; jt < 16; jt++)
                mma_tf32(acc[jt], a0, a1, a2, a3, w0p[jt*8], w1p[jt*8]);
        }
    }

    #pragma unroll
    for (int jt = 0; jt < 16; jt++) {
        int cp = jt*8 + 2*tig;
        float2 bv = *((const float2*)&bp[cp]);
        int sA = s0 + m0 + gid;
        int sB = sA + 8;
        *((float2*)(out + ((size_t)((b*Sc + sA)*Tc + t))*Cc + cp)) =
            make_float2(acc[jt][0] + bv.x, acc[jt][1] + bv.y);
        *((float2*)(out + ((size_t)((b*Sc + sB)*Tc + t))*Cc + cp)) =
            make_float2(acc[jt][2] + bv.x, acc[jt][3] + bv.y);
    }
}

// ---------------------------------------------------------------------------
extern "C" void kernel_launch(void* const* d_in, const int* in_sizes, int n_in,
                              void* d_out, int out_size) {
    const float* x    = (const float*)d_in[0];
    const void*  sidx = d_in[1];
    const float* swgt = (const float*)d_in[2];
    const float* ali  = (const float*)d_in[3];
    const float* dstp = (const float*)d_in[4];
    const float* Wq   = (const float*)d_in[5];
    const float* Wk   = (const float*)d_in[6];
    const float* Wv   = (const float*)d_in[7];
    const float* Wp   = (const float*)d_in[8];
    const float* bp   = (const float*)d_in[9];
    float* out = (float*)d_out;

    const int SM1 = (128*132 + 128*72) * 4;
    const int SM3 = (128*100 + 88*136) * 4;
    cudaFuncSetAttribute(k1_u,   cudaFuncAttributeMaxDynamicSharedMemorySize, SM1);
    cudaFuncSetAttribute(k3_out, cudaFuncAttributeMaxDynamicSharedMemorySize, SM3);

    k_detect<<<1, 256>>>((const unsigned int*)sidx);
    k0_combine<<<(Cc*UP + 255)/256, 256>>>(Wq, Wk, Wv, Wp);
    k1_u<<<Nc/128, 256, SM1>>>(x);
    k2_attn<<<Nc/4, 128>>>(x, sidx, swgt, ali, dstp);
    k3_out<<<Nc/128, 256, SM3>>>(bp, out);
}

// round 7
// speedup vs baseline: 2.3187x; 1.0577x over previous
#include <cuda_runtime.h>
#include <math.h>

#define Bc 2
#define Sc 2048
#define Tc 8
#define Cc 128
#define Kc 16
#define Hc 4
#define Dc 32
#define Fc 130        // C+2
#define BTc (Bc*Tc)   // 16
#define Nc (BTc*Sc)   // 32768
#define Uc 520        // H*(C+2)
#define UP 528        // padded row stride for U/NB
#define NBS 140       // nb row stride (conflict-free for frag loads)

typedef unsigned int u32;

// ---- scratch (__device__ globals; no allocations allowed) ----
__device__ float g_Wu[Cc*UP];             // [c][j] tf32 bits, pad j>=520 zero
__device__ float g_WoT[UP*Cc];            // [j][c'] tf32 bits, pad rows zero
__device__ float g_U[(size_t)Nc*UP];      // fp32
__device__ float g_NB[(size_t)Nc*UP];     // tf32 bits (written by k2)
__device__ int   g_is64;

__device__ __forceinline__ u32 tf32_of(float f) {
    u32 u;
    asm("cvt.rna.tf32.f32 %0, %1;" : "=r"(u) : "f"(f));
    return u;
}
__device__ __forceinline__ void mma_tf32(float* d, u32 a0, u32 a1, u32 a2, u32 a3,
                                         u32 b0, u32 b1) {
    asm("mma.sync.aligned.m16n8k8.row.col.f32.tf32.tf32.f32 "
        "{%0,%1,%2,%3}, {%4,%5,%6,%7}, {%8,%9}, {%0,%1,%2,%3};"
        : "+f"(d[0]), "+f"(d[1]), "+f"(d[2]), "+f"(d[3])
        : "r"(a0), "r"(a1), "r"(a2), "r"(a3), "r"(b0), "r"(b1));
}

// ---------------------------------------------------------------------------
__global__ void k_detect(const unsigned int* __restrict__ p) {
    __shared__ int any;
    if (threadIdx.x == 0) any = 0;
    __syncthreads();
    for (int i = threadIdx.x; i < 4096; i += blockDim.x)
        if (p[2*i + 1] != 0u) any = 1;
    __syncthreads();
    if (threadIdx.x == 0) g_is64 = (any == 0) ? 1 : 0;
}

// ---------------------------------------------------------------------------
// k0: combined weights, tf32-rounded, padded with zeros.
// ---------------------------------------------------------------------------
__global__ void k0_combine(const float* __restrict__ Wq, const float* __restrict__ Wk,
                           const float* __restrict__ Wv, const float* __restrict__ Wp) {
    int i = blockIdx.x * blockDim.x + threadIdx.x;
    if (i >= Cc*UP) return;
    int c = i / UP;
    int j = i % UP;
    float su = 0.f, so = 0.f;
    if (j < Uc) {
        int h = j / Fc;
        int f = j % Fc;
        #pragma unroll
        for (int d = 0; d < Dc; d++) {
            int hd = h*Dc + d;
            su = fmaf(Wq[hd*Cc + c], Wk[hd*(Cc+2) + f], su);
            so = fmaf(Wp[c*Cc + hd], Wv[hd*(Cc+2) + f], so);
        }
        su *= rsqrtf((float)Dc);
    }
    g_Wu[c*UP + j]  = __uint_as_float(tf32_of(su));
    g_WoT[j*Cc + c] = __uint_as_float(tf32_of(so));
}

// ---------------------------------------------------------------------------
// k1: U = X_ @ W_u via tf32 MMA (unchanged).
// ---------------------------------------------------------------------------
__global__ __launch_bounds__(256) void k1_u(const float* __restrict__ x) {
    extern __shared__ u32 sm1[];
    u32* xs = sm1;                 // 128*132
    u32* ws = sm1 + 128*132;       // 128*72
    int base = blockIdx.x * 128;
    int bt = base >> 11;
    int s0 = base & 2047;
    int b = bt >> 3, t = bt & 7;
    int tid = threadIdx.x;
    int wid = tid >> 5, lane = tid & 31, gid = lane >> 2, tig = lane & 3;
    int m0 = wid * 16;

    for (int idx = tid; idx < 4096; idx += 256) {
        int r = idx >> 5, c4 = idx & 31;
        float4 v = ((const float4*)(x + ((size_t)((b*Sc + s0 + r)*Tc + t))*Cc))[c4];
        uint4 u = make_uint4(tf32_of(v.x), tf32_of(v.y), tf32_of(v.z), tf32_of(v.w));
        *((uint4*)&xs[r*132 + c4*4]) = u;
    }
    __syncthreads();

    int rowA0 = (m0 + gid) * 132;
    int rowA1 = (m0 + gid + 8) * 132;

    for (int ch = 0; ch < 9; ch++) {
        int j0 = ch * 64;
        int jtn = (ch < 8) ? 8 : 2;
        int jw4 = jtn * 2;
        if (ch) __syncthreads();
        for (int idx = tid; idx < 128*jw4; idx += 256) {
            int c = idx / jw4, q = idx - c*jw4;
            uint4 w = ((const uint4*)(g_Wu + (size_t)c*UP + j0))[q];
            *((uint4*)&ws[c*72 + q*4]) = w;
        }
        __syncthreads();

        float acc[8][4];
        #pragma unroll
        for (int jt = 0; jt < 8; jt++)
            #pragma unroll
            for (int e = 0; e < 4; e++) acc[jt][e] = 0.f;

        #pragma unroll
        for (int ks = 0; ks < 16; ks++) {
            int kk = ks * 8;
            u32 a0 = xs[rowA0 + kk + tig];
            u32 a1 = xs[rowA1 + kk + tig];
            u32 a2 = xs[rowA0 + kk + tig + 4];
            u32 a3 = xs[rowA1 + kk + tig + 4];
            const u32* w0p = &ws[(kk + tig)*72 + gid];
            const u32* w1p = &ws[(kk + tig + 4)*72 + gid];
            #pragma unroll
            for (int jt = 0; jt < 8; jt++) {
                if (jt < jtn) {
                    mma_tf32(acc[jt], a0, a1, a2, a3, w0p[jt*8], w1p[jt*8]);
                }
            }
        }
        #pragma unroll
        for (int jt = 0; jt < 8; jt++) {
            if (jt < jtn) {
                int j = j0 + jt*8 + 2*tig;
                *((float2*)(g_U + (size_t)(base + m0 + gid    )*UP + j)) =
                    make_float2(acc[jt][0], acc[jt][1]);
                *((float2*)(g_U + (size_t)(base + m0 + gid + 8)*UP + j)) =
                    make_float2(acc[jt][2], acc[jt][3]);
            }
        }
    }
}

// ---------------------------------------------------------------------------
// k2: warp-autonomous attention; logits via tf32 MMA.
//   nb[16][140]: stride 140 -> conflict-free A-frag loads (gid*12+tig banks).
//   uT[136][4]: u transposed, tf32-rounded; heads>=4 predicated to 0.
//   Softmax in MMA fragment layout (xor shuffles over gid dim).
//   nbar stays scalar fp32 (precision guard).
// ---------------------------------------------------------------------------
__global__ __launch_bounds__(128) void k2_attn(const float* __restrict__ x,
                                               const void* __restrict__ sidx,
                                               const float* __restrict__ swgt,
                                               const float* __restrict__ ali,
                                               const float* __restrict__ dstp) {
    __shared__ __align__(16) float nb[4][Kc][NBS];     // 35.8 KB
    __shared__ __align__(16) float uT[4][136*4];       // 8.7 KB (tf32 bits)
    __shared__ __align__(16) float attn_s[4][Kc][4];   // [k][h] fp32
    __shared__ float logw[4][Kc];

    int tid = threadIdx.x;
    int n4 = tid >> 5, lane = tid & 31;
    int n = blockIdx.x * 4 + n4;
    int bt = n >> 11;
    int b = bt >> 3, t = bt & 7;
    int k = lane & 15, half = lane >> 4;
    int gid = lane >> 2, tig = lane & 3;

    // ---- P0: gather neighbors (2 lanes per k, 16 float4 each) ----
    long long jn;
    if (g_is64) jn = ((const long long*)sidx)[(size_t)n*Kc + k];
    else        jn = (long long)((const int*)sidx)[(size_t)n*Kc + k];
    const float4* src = (const float4*)(x + ((size_t)((b*Sc + (int)jn)*Tc + t)) * Cc);
    {
        int f40 = half * 16;
        #pragma unroll
        for (int q = 0; q < 16; q++)
            *((float4*)&nb[n4][k][(f40 + q)*4]) = src[f40 + q];
    }
    if (half == 0) {
        nb[n4][k][128] = ali [(size_t)n*Kc + k];
        nb[n4][k][129] = dstp[(size_t)n*Kc + k];
    } else {
        #pragma unroll
        for (int e = 0; e < 6; e++) nb[n4][k][130 + e] = 0.f;  // zero MMA pad
    }
    // uT staging: uT[f][h] = tf32(U[n][h*130+f]); f 130..135 zero
    {
        const float* Urow = g_U + (size_t)n*UP;
        #pragma unroll
        for (int i = 0; i < 17; i++) {
            int idx = lane + 32*i;          // 0..543
            int f = idx >> 2, h = idx & 3;
            float v = (f < Fc) ? Urow[h*Fc + f] : 0.f;
            uT[n4][idx] = __uint_as_float(tf32_of(v));
        }
    }
    if (lane < Kc)
        logw[n4][lane] = __logf(swgt[(size_t)n*Kc + lane] + 1e-6f);
    __syncwarp();

    // ---- P1: logits via 17 m16n8k8 tf32 MMAs. D[k][h]: rows=k, cols=h ----
    float d[4] = {0.f, 0.f, 0.f, 0.f};
    {
        const float* nbr0 = &nb[n4][gid    ][0];
        const float* nbr1 = &nb[n4][gid + 8][0];
        const float* uTp  = &uT[n4][0];
        bool hv = (gid < 4);
        #pragma unroll
        for (int ks = 0; ks < 17; ks++) {
            int kk = ks * 8;
            u32 a0 = tf32_of(nbr0[kk + tig]);
            u32 a1 = tf32_of(nbr1[kk + tig]);
            u32 a2 = tf32_of(nbr0[kk + tig + 4]);
            u32 a3 = tf32_of(nbr1[kk + tig + 4]);
            u32 b0 = hv ? __float_as_uint(uTp[(kk + tig)*4 + gid])     : 0u;
            u32 b1 = hv ? __float_as_uint(uTp[(kk + tig + 4)*4 + gid]) : 0u;
            mma_tf32(d, a0, a1, a2, a3, b0, b1);
        }
    }
    // add log-weight bias: d0,d1 are k=gid; d2,d3 are k=gid+8
    {
        float lw0 = logw[n4][gid];
        float lw1 = logw[n4][gid + 8];
        d[0] += lw0; d[1] += lw0;
        d[2] += lw1; d[3] += lw1;
    }

    // ---- P2: softmax over k (reduce over gid lanes: xor 4,8,16) ----
    {
        // head h0 = 2*tig (d0: k=gid, d2: k=gid+8)
        float m0 = fmaxf(d[0], d[2]);
        #pragma unroll
        for (int o = 4; o <= 16; o <<= 1)
            m0 = fmaxf(m0, __shfl_xor_sync(0xffffffffu, m0, o));
        float e0 = __expf(d[0] - m0), e2 = __expf(d[2] - m0);
        float s0 = e0 + e2;
        #pragma unroll
        for (int o = 4; o <= 16; o <<= 1)
            s0 += __shfl_xor_sync(0xffffffffu, s0, o);
        float a0 = e0 / s0, a2 = e2 / s0;

        // head h1 = 2*tig+1 (d1, d3)
        float m1 = fmaxf(d[1], d[3]);
        #pragma unroll
        for (int o = 4; o <= 16; o <<= 1)
            m1 = fmaxf(m1, __shfl_xor_sync(0xffffffffu, m1, o));
        float e1 = __expf(d[1] - m1), e3 = __expf(d[3] - m1);
        float s1 = e1 + e3;
        #pragma unroll
        for (int o = 4; o <= 16; o <<= 1)
            s1 += __shfl_xor_sync(0xffffffffu, s1, o);
        float a1 = e1 / s1, a3 = e3 / s1;

        if (tig < 2) {   // heads 0..3 live in tig 0,1
            attn_s[n4][gid    ][2*tig    ] = a0;
            attn_s[n4][gid    ][2*tig + 1] = a1;
            attn_s[n4][gid + 8][2*tig    ] = a2;
            attn_s[n4][gid + 8][2*tig + 1] = a3;
        }
    }
    __syncwarp();

    // ---- P3: nbar; lane = f0, scalar fp32, attn via broadcast LDS.128 ----
    {
        float4 acc[4];
        float4 acc4t = make_float4(0.f,0.f,0.f,0.f);
        #pragma unroll
        for (int q = 0; q < 4; q++) acc[q] = make_float4(0.f,0.f,0.f,0.f);
        #pragma unroll
        for (int kk = 0; kk < Kc; kk++) {
            float4 a = *((const float4*)&attn_s[n4][kk][0]);
            const float* nbr = &nb[n4][kk][0];
            #pragma unroll
            for (int q = 0; q < 4; q++) {
                float v = nbr[lane + 32*q];
                acc[q].x = fmaf(a.x, v, acc[q].x);
                acc[q].y = fmaf(a.y, v, acc[q].y);
                acc[q].z = fmaf(a.z, v, acc[q].z);
                acc[q].w = fmaf(a.w, v, acc[q].w);
            }
            if (lane < 2) {
                float v = nbr[128 + lane];
                acc4t.x = fmaf(a.x, v, acc4t.x);
                acc4t.y = fmaf(a.y, v, acc4t.y);
                acc4t.z = fmaf(a.z, v, acc4t.z);
                acc4t.w = fmaf(a.w, v, acc4t.w);
            }
        }
        u32* dst = (u32*)(g_NB + (size_t)n*UP);
        #pragma unroll
        for (int q = 0; q < 4; q++) {
            int f = lane + 32*q;
            dst[0*Fc + f] = tf32_of(acc[q].x);
            dst[1*Fc + f] = tf32_of(acc[q].y);
            dst[2*Fc + f] = tf32_of(acc[q].z);
            dst[3*Fc + f] = tf32_of(acc[q].w);
        }
        if (lane < 2) {
            int f = 128 + lane;
            dst[0*Fc + f] = tf32_of(acc4t.x);
            dst[1*Fc + f] = tf32_of(acc4t.y);
            dst[2*Fc + f] = tf32_of(acc4t.z);
            dst[3*Fc + f] = tf32_of(acc4t.w);
        }
        if (lane < 8) dst[Uc + lane] = 0u;   // zero pad cols
    }
}

// ---------------------------------------------------------------------------
// k3: OUT = NB @ W_oT + bp via tf32 MMA (unchanged).
// ---------------------------------------------------------------------------
__global__ __launch_bounds__(256) void k3_out(const float* __restrict__ bp,
                                              float* __restrict__ out) {
    extern __shared__ u32 sm3[];
    u32* as3 = sm3;                // 128*100
    u32* ws3 = sm3 + 128*100;      // 88*136
    int base = blockIdx.x * 128;
    int bt = base >> 11;
    int s0 = base & 2047;
    int b = bt >> 3, t = bt & 7;
    int tid = threadIdx.x;
    int wid = tid >> 5, lane = tid & 31, gid = lane >> 2, tig = lane & 3;
    int m0 = wid * 16;
    int rowA0 = (m0 + gid) * 100;
    int rowA1 = (m0 + gid + 8) * 100;

    float acc[16][4];
    #pragma unroll
    for (int jt = 0; jt < 16; jt++)
        #pragma unroll
        for (int e = 0; e < 4; e++) acc[jt][e] = 0.f;

    for (int ch = 0; ch < 6; ch++) {
        if (ch) __syncthreads();
        for (int idx = tid; idx < 128*22; idx += 256) {
            int r = idx / 22, q = idx - r*22;
            uint4 v = ((const uint4*)(g_NB + (size_t)(base + r)*UP + ch*88))[q];
            *((uint4*)&as3[r*100 + q*4]) = v;
        }
        for (int idx = tid; idx < 88*32; idx += 256) {
            int kk = idx >> 5, q = idx & 31;
            uint4 w = ((const uint4*)(g_WoT + (size_t)(ch*88 + kk)*Cc))[q];
            *((uint4*)&ws3[kk*136 + q*4]) = w;
        }
        __syncthreads();

        #pragma unroll
        for (int ks = 0; ks < 11; ks++) {
            int kk = ks * 8;
            u32 a0 = as3[rowA0 + kk + tig];
            u32 a1 = as3[rowA1 + kk + tig];
            u32 a2 = as3[rowA0 + kk + tig + 4];
            u32 a3 = as3[rowA1 + kk + tig + 4];
            const u32* w0p = &ws3[(kk + tig)*136 + gid];
            const u32* w1p = &ws3[(kk + tig + 4)*136 + gid];
            #pragma unroll
            for (int jt = 0; jt < 16; jt++)
                mma_tf32(acc[jt], a0, a1, a2, a3, w0p[jt*8], w1p[jt*8]);
        }
    }

    #pragma unroll
    for (int jt = 0; jt < 16; jt++) {
        int cp = jt*8 + 2*tig;
        float2 bv = *((const float2*)&bp[cp]);
        int sA = s0 + m0 + gid;
        int sB = sA + 8;
        *((float2*)(out + ((size_t)((b*Sc + sA)*Tc + t))*Cc + cp)) =
            make_float2(acc[jt][0] + bv.x, acc[jt][1] + bv.y);
        *((float2*)(out + ((size_t)((b*Sc + sB)*Tc + t))*Cc + cp)) =
            make_float2(acc[jt][2] + bv.x, acc[jt][3] + bv.y);
    }
}

// ---------------------------------------------------------------------------
extern "C" void kernel_launch(void* const* d_in, const int* in_sizes, int n_in,
                              void* d_out, int out_size) {
    const float* x    = (const float*)d_in[0];
    const void*  sidx = d_in[1];
    const float* swgt = (const float*)d_in[2];
    const float* ali  = (const float*)d_in[3];
    const float* dstp = (const float*)d_in[4];
    const float* Wq   = (const float*)d_in[5];
    const float* Wk   = (const float*)d_in[6];
    const float* Wv   = (const float*)d_in[7];
    const float* Wp   = (const float*)d_in[8];
    const float* bp   = (const float*)d_in[9];
    float* out = (float*)d_out;

    const int SM1 = (128*132 + 128*72) * 4;
    const int SM3 = (128*100 + 88*136) * 4;
    cudaFuncSetAttribute(k1_u,   cudaFuncAttributeMaxDynamicSharedMemorySize, SM1);
    cudaFuncSetAttribute(k3_out, cudaFuncAttributeMaxDynamicSharedMemorySize, SM3);

    k_detect<<<1, 256>>>((const unsigned int*)sidx);
    k0_combine<<<(Cc*UP + 255)/256, 256>>>(Wq, Wk, Wv, Wp);
    k1_u<<<Nc/128, 256, SM1>>>(x);
    k2_attn<<<Nc/4, 128>>>(x, sidx, swgt, ali, dstp);
    k3_out<<<Nc/128, 256, SM3>>>(bp, out);
}

// round 8
// speedup vs baseline: 2.9684x; 1.2802x over previous
#include <cuda_runtime.h>
#include <math.h>

#define Bc 2
#define Sc 2048
#define Tc 8
#define Cc 128
#define Kc 16
#define Hc 4
#define Dc 32
#define Fc 130        // C+2
#define BTc (Bc*Tc)   // 16
#define Nc (BTc*Sc)   // 32768
#define Uc 520        // H*(C+2)
#define UP 528        // padded row stride for U/NB
#define NBS 140       // nb row stride (conflict-free for frag loads)

typedef unsigned int u32;

// ---- scratch (__device__ globals; no allocations allowed) ----
__device__ float g_Wu[Cc*UP];             // [c][j] tf32 bits, pad j>=520 zero
__device__ float g_WoT[UP*Cc];            // [j][c'] tf32 bits, pad rows zero
__device__ float g_U[(size_t)Nc*UP];      // fp32
__device__ float g_NB[(size_t)Nc*UP];     // tf32 bits (written by k2)
__device__ int   g_is64;

__device__ __forceinline__ u32 tf32_of(float f) {
    u32 u;
    asm("cvt.rna.tf32.f32 %0, %1;" : "=r"(u) : "f"(f));
    return u;
}
__device__ __forceinline__ void mma_tf32(float* d, u32 a0, u32 a1, u32 a2, u32 a3,
                                         u32 b0, u32 b1) {
    asm("mma.sync.aligned.m16n8k8.row.col.f32.tf32.tf32.f32 "
        "{%0,%1,%2,%3}, {%4,%5,%6,%7}, {%8,%9}, {%0,%1,%2,%3};"
        : "+f"(d[0]), "+f"(d[1]), "+f"(d[2]), "+f"(d[3])
        : "r"(a0), "r"(a1), "r"(a2), "r"(a3), "r"(b0), "r"(b1));
}

// ---------------------------------------------------------------------------
__global__ void k_detect(const unsigned int* __restrict__ p) {
    __shared__ int any;
    if (threadIdx.x == 0) any = 0;
    __syncthreads();
    for (int i = threadIdx.x; i < 4096; i += blockDim.x)
        if (p[2*i + 1] != 0u) any = 1;
    __syncthreads();
    if (threadIdx.x == 0) g_is64 = (any == 0) ? 1 : 0;
}

// ---------------------------------------------------------------------------
// k0: combined weights, tf32-rounded, padded with zeros.
// ---------------------------------------------------------------------------
__global__ void k0_combine(const float* __restrict__ Wq, const float* __restrict__ Wk,
                           const float* __restrict__ Wv, const float* __restrict__ Wp) {
    int i = blockIdx.x * blockDim.x + threadIdx.x;
    if (i >= Cc*UP) return;
    int c = i / UP;
    int j = i % UP;
    float su = 0.f, so = 0.f;
    if (j < Uc) {
        int h = j / Fc;
        int f = j % Fc;
        #pragma unroll
        for (int d = 0; d < Dc; d++) {
            int hd = h*Dc + d;
            su = fmaf(Wq[hd*Cc + c], Wk[hd*(Cc+2) + f], su);
            so = fmaf(Wp[c*Cc + hd], Wv[hd*(Cc+2) + f], so);
        }
        su *= rsqrtf((float)Dc);
    }
    g_Wu[c*UP + j]  = __uint_as_float(tf32_of(su));
    g_WoT[j*Cc + c] = __uint_as_float(tf32_of(so));
}

// ---------------------------------------------------------------------------
// k1: U = X_ @ W_u via tf32 MMA (unchanged).
// ---------------------------------------------------------------------------
__global__ __launch_bounds__(256) void k1_u(const float* __restrict__ x) {
    extern __shared__ u32 sm1[];
    u32* xs = sm1;                 // 128*132
    u32* ws = sm1 + 128*132;       // 128*72
    int base = blockIdx.x * 128;
    int bt = base >> 11;
    int s0 = base & 2047;
    int b = bt >> 3, t = bt & 7;
    int tid = threadIdx.x;
    int wid = tid >> 5, lane = tid & 31, gid = lane >> 2, tig = lane & 3;
    int m0 = wid * 16;

    for (int idx = tid; idx < 4096; idx += 256) {
        int r = idx >> 5, c4 = idx & 31;
        float4 v = ((const float4*)(x + ((size_t)((b*Sc + s0 + r)*Tc + t))*Cc))[c4];
        uint4 u = make_uint4(tf32_of(v.x), tf32_of(v.y), tf32_of(v.z), tf32_of(v.w));
        *((uint4*)&xs[r*132 + c4*4]) = u;
    }
    __syncthreads();

    int rowA0 = (m0 + gid) * 132;
    int rowA1 = (m0 + gid + 8) * 132;

    for (int ch = 0; ch < 9; ch++) {
        int j0 = ch * 64;
        int jtn = (ch < 8) ? 8 : 2;
        int jw4 = jtn * 2;
        if (ch) __syncthreads();
        for (int idx = tid; idx < 128*jw4; idx += 256) {
            int c = idx / jw4, q = idx - c*jw4;
            uint4 w = ((const uint4*)(g_Wu + (size_t)c*UP + j0))[q];
            *((uint4*)&ws[c*72 + q*4]) = w;
        }
        __syncthreads();

        float acc[8][4];
        #pragma unroll
        for (int jt = 0; jt < 8; jt++)
            #pragma unroll
            for (int e = 0; e < 4; e++) acc[jt][e] = 0.f;

        #pragma unroll
        for (int ks = 0; ks < 16; ks++) {
            int kk = ks * 8;
            u32 a0 = xs[rowA0 + kk + tig];
            u32 a1 = xs[rowA1 + kk + tig];
            u32 a2 = xs[rowA0 + kk + tig + 4];
            u32 a3 = xs[rowA1 + kk + tig + 4];
            const u32* w0p = &ws[(kk + tig)*72 + gid];
            const u32* w1p = &ws[(kk + tig + 4)*72 + gid];
            #pragma unroll
            for (int jt = 0; jt < 8; jt++) {
                if (jt < jtn) {
                    mma_tf32(acc[jt], a0, a1, a2, a3, w0p[jt*8], w1p[jt*8]);
                }
            }
        }
        #pragma unroll
        for (int jt = 0; jt < 8; jt++) {
            if (jt < jtn) {
                int j = j0 + jt*8 + 2*tig;
                *((float2*)(g_U + (size_t)(base + m0 + gid    )*UP + j)) =
                    make_float2(acc[jt][0], acc[jt][1]);
                *((float2*)(g_U + (size_t)(base + m0 + gid + 8)*UP + j)) =
                    make_float2(acc[jt][2], acc[jt][3]);
            }
        }
    }
}

// ---------------------------------------------------------------------------
// k2: warp-autonomous attention; coalesced gather (8 lanes per neighbor row:
// each LDG.128 covers 4 rows x 128B aligned => 4 L1 wavefronts, not 32),
// logits via tf32 MMA, fragment softmax, scalar fp32 nbar.
// ---------------------------------------------------------------------------
__global__ __launch_bounds__(128) void k2_attn(const float* __restrict__ x,
                                               const void* __restrict__ sidx,
                                               const float* __restrict__ swgt,
                                               const float* __restrict__ ali,
                                               const float* __restrict__ dstp) {
    __shared__ __align__(16) float nb[4][Kc][NBS];     // 35.8 KB
    __shared__ __align__(16) float uT[4][136*4];       // 8.7 KB (tf32 bits)
    __shared__ __align__(16) float attn_s[4][Kc][4];   // [k][h] fp32
    __shared__ float logw[4][Kc];

    int tid = threadIdx.x;
    int n4 = tid >> 5, lane = tid & 31;
    int n = blockIdx.x * 4 + n4;
    int bt = n >> 11;
    int b = bt >> 3, t = bt & 7;
    int k = lane & 15, half = lane >> 4;
    int gid = lane >> 2, tig = lane & 3;

    // ---- P0: neighbor index (one per k, lanes 0-15 authoritative) ----
    int myjn;
    if (g_is64) myjn = (int)((const long long*)sidx)[(size_t)n*Kc + k];
    else        myjn = ((const int*)sidx)[(size_t)n*Kc + k];

    // coalesced gather: kg = lane>>3 (4 rows per pass), l8 = lane&7
    {
        int kg = lane >> 3, l8 = lane & 7;
        size_t xbase = ((size_t)(b*Sc))*Tc*Cc + (size_t)t*Cc;
        #pragma unroll
        for (int set = 0; set < 4; set++) {
            int kk = set*4 + kg;
            int jn_kk = __shfl_sync(0xffffffffu, myjn, kk);
            const float4* srck = (const float4*)(x + xbase + (size_t)jn_kk*Tc*Cc);
            #pragma unroll
            for (int q = 0; q < 4; q++) {
                int f4 = l8 + 8*q;
                *((float4*)&nb[n4][kk][f4*4]) = srck[f4];
            }
        }
    }
    if (half == 0) {
        nb[n4][k][128] = ali [(size_t)n*Kc + k];
        nb[n4][k][129] = dstp[(size_t)n*Kc + k];
    } else {
        #pragma unroll
        for (int e = 0; e < 6; e++) nb[n4][k][130 + e] = 0.f;  // zero MMA pad
    }
    // uT staging: uT[f][h] = tf32(U[n][h*130+f]); f 130..135 zero
    {
        const float* Urow = g_U + (size_t)n*UP;
        #pragma unroll
        for (int i = 0; i < 17; i++) {
            int idx = lane + 32*i;          // 0..543
            int f = idx >> 2, h = idx & 3;
            float v = (f < Fc) ? Urow[h*Fc + f] : 0.f;
            uT[n4][idx] = __uint_as_float(tf32_of(v));
        }
    }
    if (lane < Kc)
        logw[n4][lane] = __logf(swgt[(size_t)n*Kc + lane] + 1e-6f);
    __syncwarp();

    // ---- P1: logits via 17 m16n8k8 tf32 MMAs. D[k][h]: rows=k, cols=h ----
    float d[4] = {0.f, 0.f, 0.f, 0.f};
    {
        const float* nbr0 = &nb[n4][gid    ][0];
        const float* nbr1 = &nb[n4][gid + 8][0];
        const float* uTp  = &uT[n4][0];
        bool hv = (gid < 4);
        #pragma unroll
        for (int ks = 0; ks < 17; ks++) {
            int kk = ks * 8;
            u32 a0 = tf32_of(nbr0[kk + tig]);
            u32 a1 = tf32_of(nbr1[kk + tig]);
            u32 a2 = tf32_of(nbr0[kk + tig + 4]);
            u32 a3 = tf32_of(nbr1[kk + tig + 4]);
            u32 b0 = hv ? __float_as_uint(uTp[(kk + tig)*4 + gid])     : 0u;
            u32 b1 = hv ? __float_as_uint(uTp[(kk + tig + 4)*4 + gid]) : 0u;
            mma_tf32(d, a0, a1, a2, a3, b0, b1);
        }
    }
    // add log-weight bias: d0,d1 are k=gid; d2,d3 are k=gid+8
    {
        float lw0 = logw[n4][gid];
        float lw1 = logw[n4][gid + 8];
        d[0] += lw0; d[1] += lw0;
        d[2] += lw1; d[3] += lw1;
    }

    // ---- P2: softmax over k (reduce over gid lanes: xor 4,8,16) ----
    {
        float m0 = fmaxf(d[0], d[2]);
        #pragma unroll
        for (int o = 4; o <= 16; o <<= 1)
            m0 = fmaxf(m0, __shfl_xor_sync(0xffffffffu, m0, o));
        float e0 = __expf(d[0] - m0), e2 = __expf(d[2] - m0);
        float s0 = e0 + e2;
        #pragma unroll
        for (int o = 4; o <= 16; o <<= 1)
            s0 += __shfl_xor_sync(0xffffffffu, s0, o);
        float a0 = e0 / s0, a2 = e2 / s0;

        float m1 = fmaxf(d[1], d[3]);
        #pragma unroll
        for (int o = 4; o <= 16; o <<= 1)
            m1 = fmaxf(m1, __shfl_xor_sync(0xffffffffu, m1, o));
        float e1 = __expf(d[1] - m1), e3 = __expf(d[3] - m1);
        float s1 = e1 + e3;
        #pragma unroll
        for (int o = 4; o <= 16; o <<= 1)
            s1 += __shfl_xor_sync(0xffffffffu, s1, o);
        float a1 = e1 / s1, a3 = e3 / s1;

        if (tig < 2) {   // heads 0..3 live in tig 0,1
            attn_s[n4][gid    ][2*tig    ] = a0;
            attn_s[n4][gid    ][2*tig + 1] = a1;
            attn_s[n4][gid + 8][2*tig    ] = a2;
            attn_s[n4][gid + 8][2*tig + 1] = a3;
        }
    }
    __syncwarp();

    // ---- P3: nbar; lane = f0, scalar fp32, attn via broadcast LDS.128 ----
    {
        float4 acc[4];
        float4 acc4t = make_float4(0.f,0.f,0.f,0.f);
        #pragma unroll
        for (int q = 0; q < 4; q++) acc[q] = make_float4(0.f,0.f,0.f,0.f);
        #pragma unroll
        for (int kk = 0; kk < Kc; kk++) {
            float4 a = *((const float4*)&attn_s[n4][kk][0]);
            const float* nbr = &nb[n4][kk][0];
            #pragma unroll
            for (int q = 0; q < 4; q++) {
                float v = nbr[lane + 32*q];
                acc[q].x = fmaf(a.x, v, acc[q].x);
                acc[q].y = fmaf(a.y, v, acc[q].y);
                acc[q].z = fmaf(a.z, v, acc[q].z);
                acc[q].w = fmaf(a.w, v, acc[q].w);
            }
            if (lane < 2) {
                float v = nbr[128 + lane];
                acc4t.x = fmaf(a.x, v, acc4t.x);
                acc4t.y = fmaf(a.y, v, acc4t.y);
                acc4t.z = fmaf(a.z, v, acc4t.z);
                acc4t.w = fmaf(a.w, v, acc4t.w);
            }
        }
        u32* dst = (u32*)(g_NB + (size_t)n*UP);
        #pragma unroll
        for (int q = 0; q < 4; q++) {
            int f = lane + 32*q;
            dst[0*Fc + f] = tf32_of(acc[q].x);
            dst[1*Fc + f] = tf32_of(acc[q].y);
            dst[2*Fc + f] = tf32_of(acc[q].z);
            dst[3*Fc + f] = tf32_of(acc[q].w);
        }
        if (lane < 2) {
            int f = 128 + lane;
            dst[0*Fc + f] = tf32_of(acc4t.x);
            dst[1*Fc + f] = tf32_of(acc4t.y);
            dst[2*Fc + f] = tf32_of(acc4t.z);
            dst[3*Fc + f] = tf32_of(acc4t.w);
        }
        if (lane < 8) dst[Uc + lane] = 0u;   // zero pad cols
    }
}

// ---------------------------------------------------------------------------
// k3: OUT = NB @ W_oT + bp via tf32 MMA (unchanged).
// ---------------------------------------------------------------------------
__global__ __launch_bounds__(256) void k3_out(const float* __restrict__ bp,
                                              float* __restrict__ out) {
    extern __shared__ u32 sm3[];
    u32* as3 = sm3;                // 128*100
    u32* ws3 = sm3 + 128*100;      // 88*136
    int base = blockIdx.x * 128;
    int bt = base >> 11;
    int s0 = base & 2047;
    int b = bt >> 3, t = bt & 7;
    int tid = threadIdx.x;
    int wid = tid >> 5, lane = tid & 31, gid = lane >> 2, tig = lane & 3;
    int m0 = wid * 16;
    int rowA0 = (m0 + gid) * 100;
    int rowA1 = (m0 + gid + 8) * 100;

    float acc[16][4];
    #pragma unroll
    for (int jt = 0; jt < 16; jt++)
        #pragma unroll
        for (int e = 0; e < 4; e++) acc[jt][e] = 0.f;

    for (int ch = 0; ch < 6; ch++) {
        if (ch) __syncthreads();
        for (int idx = tid; idx < 128*22; idx += 256) {
            int r = idx / 22, q = idx - r*22;
            uint4 v = ((const uint4*)(g_NB + (size_t)(base + r)*UP + ch*88))[q];
            *((uint4*)&as3[r*100 + q*4]) = v;
        }
        for (int idx = tid; idx < 88*32; idx += 256) {
            int kk = idx >> 5, q = idx & 31;
            uint4 w = ((const uint4*)(g_WoT + (size_t)(ch*88 + kk)*Cc))[q];
            *((uint4*)&ws3[kk*136 + q*4]) = w;
        }
        __syncthreads();

        #pragma unroll
        for (int ks = 0; ks < 11; ks++) {
            int kk = ks * 8;
            u32 a0 = as3[rowA0 + kk + tig];
            u32 a1 = as3[rowA1 + kk + tig];
            u32 a2 = as3[rowA0 + kk + tig + 4];
            u32 a3 = as3[rowA1 + kk + tig + 4];
            const u32* w0p = &ws3[(kk + tig)*136 + gid];
            const u32* w1p = &ws3[(kk + tig + 4)*136 + gid];
            #pragma unroll
            for (int jt = 0; jt < 16; jt++)
                mma_tf32(acc[jt], a0, a1, a2, a3, w0p[jt*8], w1p[jt*8]);
        }
    }

    #pragma unroll
    for (int jt = 0; jt < 16; jt++) {
        int cp = jt*8 + 2*tig;
        float2 bv = *((const float2*)&bp[cp]);
        int sA = s0 + m0 + gid;
        int sB = sA + 8;
        *((float2*)(out + ((size_t)((b*Sc + sA)*Tc + t))*Cc + cp)) =
            make_float2(acc[jt][0] + bv.x, acc[jt][1] + bv.y);
        *((float2*)(out + ((size_t)((b*Sc + sB)*Tc + t))*Cc + cp)) =
            make_float2(acc[jt][2] + bv.x, acc[jt][3] + bv.y);
    }
}

// ---------------------------------------------------------------------------
extern "C" void kernel_launch(void* const* d_in, const int* in_sizes, int n_in,
                              void* d_out, int out_size) {
    const float* x    = (const float*)d_in[0];
    const void*  sidx = d_in[1];
    const float* swgt = (const float*)d_in[2];
    const float* ali  = (const float*)d_in[3];
    const float* dstp = (const float*)d_in[4];
    const float* Wq   = (const float*)d_in[5];
    const float* Wk   = (const float*)d_in[6];
    const float* Wv   = (const float*)d_in[7];
    const float* Wp   = (const float*)d_in[8];
    const float* bp   = (const float*)d_in[9];
    float* out = (float*)d_out;

    const int SM1 = (128*132 + 128*72) * 4;
    const int SM3 = (128*100 + 88*136) * 4;
    cudaFuncSetAttribute(k1_u,   cudaFuncAttributeMaxDynamicSharedMemorySize, SM1);
    cudaFuncSetAttribute(k3_out, cudaFuncAttributeMaxDynamicSharedMemorySize, SM3);

    k_detect<<<1, 256>>>((const unsigned int*)sidx);
    k0_combine<<<(Cc*UP + 255)/256, 256>>>(Wq, Wk, Wv, Wp);
    k1_u<<<Nc/128, 256, SM1>>>(x);
    k2_attn<<<Nc/4, 128>>>(x, sidx, swgt, ali, dstp);
    k3_out<<<Nc/128, 256, SM3>>>(bp, out);
}